// round 6
// baseline (speedup 1.0000x reference)
#include <cuda_runtime.h>
#include <cstdint>
#include <cstddef>

#define NN 10000
#define NE 320000
#define FIN 512
#define HH 256

// ---------------- scratch (device globals; no allocation) ----------------
__device__ float g_Xs[NN * HH];
__device__ float g_Xd[NN * HH];
__device__ float g_agg[NN * HH];
__device__ float g_deg[NN];
__device__ float g_P[NN * HH];
__device__ float g_x1h[NN * HH];
__device__ float g_x1[NN * HH];
__device__ float g_Y1[NN * HH];
__device__ float g_Y2[NN * HH];
__device__ float g_EA1[(size_t)NE * HH];

// ---------------- f32x2 helpers ----------------
__device__ __forceinline__ unsigned long long pack2(float v) {
    unsigned long long r;
    unsigned int u = __float_as_uint(v);
    asm("mov.b64 %0, {%1,%1};" : "=l"(r) : "r"(u));
    return r;
}
__device__ __forceinline__ void fma2(unsigned long long& acc, unsigned long long a, unsigned long long b) {
    asm("fma.rn.f32x2 %0, %1, %2, %0;" : "+l"(acc) : "l"(a), "l"(b));
}
__device__ __forceinline__ float2 unpack2(unsigned long long v) {
    unsigned int lo, hi;
    asm("mov.b64 {%0,%1}, %2;" : "=r"(lo), "=r"(hi) : "l"(v));
    return make_float2(__uint_as_float(lo), __uint_as_float(hi));
}

// ---------------- utility kernels ----------------
__global__ void k_zero() {
    int idx = blockIdx.x * blockDim.x + threadIdx.x;
    const int total = NN * HH + NN;
    for (; idx < total; idx += gridDim.x * blockDim.x) {
        if (idx < NN * HH) g_agg[idx] = 0.f;
        else g_deg[idx - NN * HH] = 0.f;
    }
}
__global__ void k_deg(const int* __restrict__ ei) {
    int e = blockIdx.x * 256 + threadIdx.x;
    if (e < NE) atomicAdd(&g_deg[ei[NE + e]], 1.0f);
}
__global__ void k_scale() {
    int idx = blockIdx.x * 256 + threadIdx.x;
    if (idx < NN * HH) g_agg[idx] = g_agg[idx] / fmaxf(g_deg[idx >> 8], 1.0f);
}

// ------- generic fp32 GEMM: C = act(A[M,K] @ W[K,256](ld=256) + bias + addC) -------
__global__ __launch_bounds__(256) void k_sgemm(
    const float* __restrict__ A, const float* __restrict__ W,
    const float* __restrict__ bias, const float* __restrict__ addC,
    float* __restrict__ C, int M, int K, int relu)
{
    __shared__ float As[16][64];
    __shared__ float Ws[16][64];
    int tid = threadIdx.x;
    int tx = tid & 15, ty = tid >> 4;
    int row0 = blockIdx.x * 64, col0 = blockIdx.y * 64;
    float acc[4][4] = {};
    int ar = tid >> 2, ac = (tid & 3) << 2;
    int wr = tid >> 4, wc = (tid & 15) << 2;
    for (int k0 = 0; k0 < K; k0 += 16) {
        float4 av = make_float4(0.f, 0.f, 0.f, 0.f);
        if (row0 + ar < M) av = *(const float4*)(A + (size_t)(row0 + ar) * K + k0 + ac);
        As[ac + 0][ar] = av.x; As[ac + 1][ar] = av.y;
        As[ac + 2][ar] = av.z; As[ac + 3][ar] = av.w;
        *(float4*)&Ws[wr][wc] = *(const float4*)(W + (size_t)(k0 + wr) * HH + col0 + wc);
        __syncthreads();
#pragma unroll
        for (int k = 0; k < 16; k++) {
            float a[4], w[4];
#pragma unroll
            for (int i = 0; i < 4; i++) a[i] = As[k][ty * 4 + i];
#pragma unroll
            for (int j = 0; j < 4; j++) w[j] = Ws[k][tx * 4 + j];
#pragma unroll
            for (int i = 0; i < 4; i++)
#pragma unroll
                for (int j = 0; j < 4; j++) acc[i][j] += a[i] * w[j];
        }
        __syncthreads();
    }
#pragma unroll
    for (int i = 0; i < 4; i++) {
        int r = row0 + ty * 4 + i;
        if (r >= M) continue;
#pragma unroll
        for (int j = 0; j < 4; j++) {
            int c = col0 + tx * 4 + j;
            float v = acc[i][j];
            if (bias) v += bias[c];
            if (addC) v += addC[(size_t)r * HH + c];
            if (relu) v = fmaxf(v, 0.f);
            C[(size_t)r * HH + c] = v;
        }
    }
}

// ---------------- fused edge layer 0 ----------------
// EA1[e] = relu(Xs[src]+Xd[dst]+ea@W3+be0a) @ We0b + be0b ; agg[dst] += EA1[e]
__global__ __launch_bounds__(256) void k_edge_gemm0(
    const int* __restrict__ ei, const float* __restrict__ eattr,
    const float* __restrict__ We0a, const float* __restrict__ be0a,
    const float* __restrict__ We0b, const float* __restrict__ be0b)
{
    __shared__ float As[8][64];
    __shared__ float Ws[8 * 256];
    __shared__ float w3f[256 * 6];
    __shared__ float b0s[256];
    __shared__ float ea_s[64][6];
    __shared__ int src_s[64], dst_s[64];

    int tid = threadIdx.x;
    int e0 = blockIdx.x * 64;
    if (tid < 64) { src_s[tid] = ei[e0 + tid]; dst_s[tid] = ei[NE + e0 + tid]; }
    b0s[tid] = be0a[tid];
    for (int idx = tid; idx < 1536; idx += 256) {
        int j = idx >> 8, k = idx & 255;
        w3f[k * 6 + j] = We0a[(size_t)(1024 + j) * HH + k];
    }
    for (int idx = tid; idx < 384; idx += 256)
        ea_s[idx / 6][idx % 6] = eattr[(size_t)(e0 + idx / 6) * 6 + (idx % 6)];
    __syncthreads();

    int ty = tid >> 5, tx = tid & 31;
    int am = tid >> 2, ak = (tid & 3) << 1;
    int wr = tid >> 5, wc = (tid & 31) << 2;
    const float* xs_row = g_Xs + (size_t)src_s[am] * HH;
    const float* xd_row = g_Xd + (size_t)dst_s[am] * HH;
    float ear[6];
#pragma unroll
    for (int j = 0; j < 6; j++) ear[j] = ea_s[am][j];

    unsigned long long acc[8][4];
#pragma unroll
    for (int i = 0; i < 8; i++)
#pragma unroll
        for (int jp = 0; jp < 4; jp++) acc[i][jp] = 0ull;

    // prefetch chunk 0
    float2 xs = *(const float2*)(xs_row + ak);
    float2 xd = *(const float2*)(xd_row + ak);
    float4 wp0 = *(const float4*)(We0b + (size_t)wr * HH + wc);
    float4 wp1 = *(const float4*)(We0b + (size_t)wr * HH + wc + 128);

    for (int k0 = 0; k0 < 256; k0 += 8) {
        int kg = k0 + ak;
        float v0 = xs.x + xd.x + b0s[kg];
        float v1 = xs.y + xd.y + b0s[kg + 1];
#pragma unroll
        for (int j = 0; j < 6; j++) {
            v0 += ear[j] * w3f[kg * 6 + j];
            v1 += ear[j] * w3f[(kg + 1) * 6 + j];
        }
        As[ak][am]     = fmaxf(v0, 0.f);
        As[ak + 1][am] = fmaxf(v1, 0.f);
        *(float4*)(Ws + wr * 256 + wc)       = wp0;
        *(float4*)(Ws + wr * 256 + wc + 128) = wp1;
        __syncthreads();
        if (k0 + 8 < 256) {
            xs = *(const float2*)(xs_row + kg + 8);
            xd = *(const float2*)(xd_row + kg + 8);
            wp0 = *(const float4*)(We0b + (size_t)(k0 + 8 + wr) * HH + wc);
            wp1 = *(const float4*)(We0b + (size_t)(k0 + 8 + wr) * HH + wc + 128);
        }
#pragma unroll
        for (int k = 0; k < 8; k++) {
            unsigned long long w2[4];
#pragma unroll
            for (int jp = 0; jp < 4; jp++)
                w2[jp] = *(const unsigned long long*)(Ws + k * 256 + (tx << 1) + (jp << 6));
#pragma unroll
            for (int i = 0; i < 8; i++) {
                unsigned long long a2 = pack2(As[k][ty * 8 + i]);
#pragma unroll
                for (int jp = 0; jp < 4; jp++) fma2(acc[i][jp], a2, w2[jp]);
            }
        }
        __syncthreads();
    }
#pragma unroll
    for (int i = 0; i < 8; i++) {
        int m = ty * 8 + i;
        size_t rbase = (size_t)(e0 + m) * HH;
        int d = dst_s[m];
#pragma unroll
        for (int jp = 0; jp < 4; jp++) {
            int c = (tx << 1) + (jp << 6);
            float2 v = unpack2(acc[i][jp]);
            v.x += be0b[c];
            v.y += be0b[c + 1];
            *(float2*)(g_EA1 + rbase + c) = v;
            atomicAdd(&g_agg[(size_t)d * HH + c], v.x);
            atomicAdd(&g_agg[(size_t)d * HH + c + 1], v.y);
        }
    }
}

// ----- chain2 tile GEMM: acc += Asm[64x256] @ Wg[256x256], W staged via smem -----
__device__ __forceinline__ void tile_gemm(const float* __restrict__ Asm, const float* __restrict__ Wg,
                                          float* __restrict__ Wsm, unsigned long long (&acc)[8][4],
                                          int tid, int ty, int tx)
{
    int wr = tid >> 5, wc = (tid & 31) << 2;
    float4 wp0 = *(const float4*)(Wg + (size_t)wr * HH + wc);
    float4 wp1 = *(const float4*)(Wg + (size_t)wr * HH + wc + 128);
    for (int k0 = 0; k0 < 256; k0 += 8) {
        *(float4*)(Wsm + wr * 256 + wc)       = wp0;
        *(float4*)(Wsm + wr * 256 + wc + 128) = wp1;
        __syncthreads();
        if (k0 + 8 < 256) {
            wp0 = *(const float4*)(Wg + (size_t)(k0 + 8 + wr) * HH + wc);
            wp1 = *(const float4*)(Wg + (size_t)(k0 + 8 + wr) * HH + wc + 128);
        }
#pragma unroll
        for (int k = 0; k < 8; k++) {
            unsigned long long w2[4];
#pragma unroll
            for (int jp = 0; jp < 4; jp++)
                w2[jp] = *(const unsigned long long*)(Wsm + k * 256 + (tx << 1) + (jp << 6));
#pragma unroll
            for (int i = 0; i < 8; i++) {
                unsigned long long a2 = pack2(Asm[(ty * 8 + i) * 256 + k0 + k]);
#pragma unroll
                for (int jp = 0; jp < 4; jp++) fma2(acc[i][jp], a2, w2[jp]);
            }
        }
        __syncthreads();
    }
}

// ---------------- fused edge layer 1 + predictor ----------------
__global__ __launch_bounds__(256, 1) void k_chain2(
    const int* __restrict__ ei,
    const float* __restrict__ We1a, const float* __restrict__ be1a,
    const float* __restrict__ We1b, const float* __restrict__ be1b,
    const float* __restrict__ Wp1,  const float* __restrict__ bp1,
    const float* __restrict__ Wp2,  const float* __restrict__ bp2,
    float* __restrict__ out)
{
    extern __shared__ float sm[];
    float* A_sm = sm;                 // 64*256 : EA1, later EA2
    float* B_sm = sm + 64 * 256;      // 64*256 : h1
    float* W_sm = sm + 2 * 64 * 256;  // 8*256
    __shared__ int src_s[64], dst_s[64];
    __shared__ float wp2s[256];

    int tid = threadIdx.x;
    int e0 = blockIdx.x * 64;
    if (tid < 64) { src_s[tid] = ei[e0 + tid]; dst_s[tid] = ei[NE + e0 + tid]; }
    wp2s[tid] = Wp2[tid];
#pragma unroll
    for (int it = 0; it < 16; it++) {
        int lin = it * 256 + tid;
        int r = lin >> 6, c4 = (lin & 63) << 2;
        *(float4*)(A_sm + r * 256 + c4) = *(const float4*)(g_EA1 + (size_t)(e0 + r) * HH + c4);
    }
    __syncthreads();

    int ty = tid >> 5, tx = tid & 31;
    unsigned long long acc[8][4];

    // GEMM1: h1 = relu(EA1 @ We1a[512:768] + Y1[src] + Y2[dst] + be1a)
#pragma unroll
    for (int i = 0; i < 8; i++)
#pragma unroll
        for (int jp = 0; jp < 4; jp++) acc[i][jp] = 0ull;
    tile_gemm(A_sm, We1a + 512 * HH, W_sm, acc, tid, ty, tx);
#pragma unroll
    for (int i = 0; i < 8; i++) {
        int m = ty * 8 + i;
        const float* y1r = g_Y1 + (size_t)src_s[m] * HH;
        const float* y2r = g_Y2 + (size_t)dst_s[m] * HH;
#pragma unroll
        for (int jp = 0; jp < 4; jp++) {
            int c = (tx << 1) + (jp << 6);
            float2 v = unpack2(acc[i][jp]);
            v.x += be1a[c]     + y1r[c]     + y2r[c];
            v.y += be1a[c + 1] + y1r[c + 1] + y2r[c + 1];
            B_sm[m * 256 + c]     = fmaxf(v.x, 0.f);
            B_sm[m * 256 + c + 1] = fmaxf(v.y, 0.f);
        }
    }
    __syncthreads();

    // GEMM2: EA2 = h1 @ We1b + be1b + EA1  (in-place into A_sm)
#pragma unroll
    for (int i = 0; i < 8; i++)
#pragma unroll
        for (int jp = 0; jp < 4; jp++) acc[i][jp] = 0ull;
    tile_gemm(B_sm, We1b, W_sm, acc, tid, ty, tx);
#pragma unroll
    for (int i = 0; i < 8; i++) {
        int m = ty * 8 + i;
#pragma unroll
        for (int jp = 0; jp < 4; jp++) {
            int c = (tx << 1) + (jp << 6);
            float2 v = unpack2(acc[i][jp]);
            A_sm[m * 256 + c]     = v.x + be1b[c]     + A_sm[m * 256 + c];
            A_sm[m * 256 + c + 1] = v.y + be1b[c + 1] + A_sm[m * 256 + c + 1];
        }
    }
    __syncthreads();

    // GEMM3: h = leaky_relu(EA2 @ Wp1 + bp1); out = h . wp2 + bp2
#pragma unroll
    for (int i = 0; i < 8; i++)
#pragma unroll
        for (int jp = 0; jp < 4; jp++) acc[i][jp] = 0ull;
    tile_gemm(A_sm, Wp1, W_sm, acc, tid, ty, tx);
#pragma unroll
    for (int i = 0; i < 8; i++) {
        float p = 0.f;
#pragma unroll
        for (int jp = 0; jp < 4; jp++) {
            int c = (tx << 1) + (jp << 6);
            float2 v = unpack2(acc[i][jp]);
            float h0v = v.x + bp1[c];
            h0v = (h0v > 0.f) ? h0v : 0.01f * h0v;
            p += h0v * wp2s[c];
            float h1v = v.y + bp1[c + 1];
            h1v = (h1v > 0.f) ? h1v : 0.01f * h1v;
            p += h1v * wp2s[c + 1];
        }
#pragma unroll
        for (int off = 16; off > 0; off >>= 1) p += __shfl_xor_sync(0xffffffffu, p, off);
        if (tx == 0) out[e0 + ty * 8 + i] = p + bp2[0];
    }
}

// ---------------- host launcher ----------------
extern "C" void kernel_launch(void* const* d_in, const int* in_sizes, int n_in,
                              void* d_out, int out_size)
{
    (void)in_sizes; (void)n_in; (void)out_size;
    const float* x    = (const float*)d_in[0];
    const int*   ei   = (const int*)  d_in[1];
    const float* ea   = (const float*)d_in[2];
    const float* We0a = (const float*)d_in[3];
    const float* be0a = (const float*)d_in[4];
    const float* We0b = (const float*)d_in[5];
    const float* be0b = (const float*)d_in[6];
    const float* Wn0a = (const float*)d_in[7];
    const float* bn0a = (const float*)d_in[8];
    const float* Wn0b = (const float*)d_in[9];
    const float* bn0b = (const float*)d_in[10];
    const float* We1a = (const float*)d_in[11];
    const float* be1a = (const float*)d_in[12];
    const float* We1b = (const float*)d_in[13];
    const float* be1b = (const float*)d_in[14];
    // d_in[15..18] = Wn1a,bn1a,Wn1b,bn1b : dead code (x2 never reaches the output)
    const float* Wp1  = (const float*)d_in[19];
    const float* bp1  = (const float*)d_in[20];
    const float* Wp2  = (const float*)d_in[21];
    const float* bp2  = (const float*)d_in[22];
    float* out = (float*)d_out;

    cudaFuncSetAttribute(k_chain2, cudaFuncAttributeMaxDynamicSharedMemorySize, 139264);

    void *p_Xs, *p_Xd, *p_agg, *p_P, *p_x1h, *p_x1, *p_Y1, *p_Y2;
    cudaGetSymbolAddress(&p_Xs,  g_Xs);
    cudaGetSymbolAddress(&p_Xd,  g_Xd);
    cudaGetSymbolAddress(&p_agg, g_agg);
    cudaGetSymbolAddress(&p_P,   g_P);
    cudaGetSymbolAddress(&p_x1h, g_x1h);
    cudaGetSymbolAddress(&p_x1,  g_x1);
    cudaGetSymbolAddress(&p_Y1,  g_Y1);
    cudaGetSymbolAddress(&p_Y2,  g_Y2);

    dim3 gN((NN + 63) / 64, 4);

    k_zero<<<2048, 256>>>();
    k_deg<<<NE / 256, 256>>>(ei);

    // layer-0 edge precompute: Xs = x@We0a[0:512], Xd = x@We0a[512:1024]
    k_sgemm<<<gN, 256>>>(x, We0a,            nullptr, nullptr, (float*)p_Xs, NN, FIN, 0);
    k_sgemm<<<gN, 256>>>(x, We0a + 512 * HH, nullptr, nullptr, (float*)p_Xd, NN, FIN, 0);

    // fused edge layer 0 -> EA1, agg(+=)
    k_edge_gemm0<<<NE / 64, 256>>>(ei, ea, We0a, be0a, We0b, be0b);
    k_scale<<<(NN * HH + 255) / 256, 256>>>();

    // node MLP 0: x1 = relu(x@Wn0a_top + agg@Wn0a_bot + bn0a) @ Wn0b + bn0b
    k_sgemm<<<gN, 256>>>(x, Wn0a, nullptr, nullptr, (float*)p_P, NN, FIN, 0);
    k_sgemm<<<gN, 256>>>((const float*)p_agg, Wn0a + 512 * HH, bn0a, (const float*)p_P,
                         (float*)p_x1h, NN, HH, 1);
    k_sgemm<<<gN, 256>>>((const float*)p_x1h, Wn0b, bn0b, nullptr, (float*)p_x1, NN, HH, 0);

    // layer-1 edge precompute: Y1 = x1@We1a[0:256], Y2 = x1@We1a[256:512]
    k_sgemm<<<gN, 256>>>((const float*)p_x1, We1a,            nullptr, nullptr, (float*)p_Y1, NN, HH, 0);
    k_sgemm<<<gN, 256>>>((const float*)p_x1, We1a + 256 * HH, nullptr, nullptr, (float*)p_Y2, NN, HH, 0);

    // fused edge layer 1 + residual + predictor
    k_chain2<<<NE / 64, 256, 139264>>>(ei, We1a, be1a, We1b, be1b, Wp1, bp1, Wp2, bp2, out);
}

// round 9
// speedup vs baseline: 1.2616x; 1.2616x over previous
#include <cuda_runtime.h>
#include <cuda_bf16.h>
#include <cstdint>
#include <cstddef>

#define NN 10000
#define NE 320000
#define FIN 512
#define HH 256
#define SA 264   // A smem row stride (bf16 elems): 528B -> 4-bank shift/row
#define SB 24    // B smem row stride (bf16 elems): 48B -> 12-bank shift/row

// ---------------- scratch ----------------
__device__ float g_Xs[NN * HH];
__device__ float g_Xd[NN * HH];
__device__ float g_agg[NN * HH];
__device__ float g_deg[NN];
__device__ float g_P[NN * HH];
__device__ float g_x1h[NN * HH];
__device__ float g_x1[NN * HH];
__device__ float g_Y1[NN * HH];
__device__ float g_Y2[NN * HH];
__device__ float g_EA1[(size_t)NE * HH];
// 4 weights, bf16 hi/lo, layout [w][n][k] (k contiguous = col-major B)
__device__ __align__(128) __nv_bfloat16 g_Wh[4 * 65536];
__device__ __align__(128) __nv_bfloat16 g_Wl[4 * 65536];

// ---------------- helpers ----------------
__device__ __forceinline__ void mma_bf16(float* c, unsigned a0, unsigned a1, unsigned a2,
                                         unsigned a3, unsigned b0, unsigned b1) {
    asm volatile(
        "mma.sync.aligned.m16n8k16.row.col.f32.bf16.bf16.f32 "
        "{%0,%1,%2,%3}, {%4,%5,%6,%7}, {%8,%9}, {%0,%1,%2,%3};"
        : "+f"(c[0]), "+f"(c[1]), "+f"(c[2]), "+f"(c[3])
        : "r"(a0), "r"(a1), "r"(a2), "r"(a3), "r"(b0), "r"(b1));
}

// split fp32 pair -> bf16 hi/lo packed words
__device__ __forceinline__ void split2(float v0, float v1, unsigned& hp, unsigned& lp) {
    __nv_bfloat16 h0 = __float2bfloat16(v0), h1 = __float2bfloat16(v1);
    __nv_bfloat16 l0 = __float2bfloat16(v0 - __bfloat162float(h0));
    __nv_bfloat16 l1 = __float2bfloat16(v1 - __bfloat162float(h1));
    hp = (unsigned)__bfloat16_as_ushort(h0) | ((unsigned)__bfloat16_as_ushort(h1) << 16);
    lp = (unsigned)__bfloat16_as_ushort(l0) | ((unsigned)__bfloat16_as_ushort(l1) << 16);
}
__device__ __forceinline__ void split_store(__nv_bfloat16* Ah, __nv_bfloat16* Al,
                                            int m, int k, float v0, float v1) {
    unsigned hp, lp;
    split2(v0, v1, hp, lp);
    *(unsigned*)(Ah + m * SA + k) = hp;
    *(unsigned*)(Al + m * SA + k) = lp;
}

// ---- core warp-mma GEMM: acc[16][4] += A(64x256 smem hi/lo) @ W[wsel](256x256) ----
__device__ __forceinline__ void mma_gemm(
    const __nv_bfloat16* Ah, const __nv_bfloat16* Al,
    __nv_bfloat16* Bh, __nv_bfloat16* Bl,
    int wsel, float (&acc)[16][4], int tid)
{
    const __nv_bfloat16* gWh = g_Wh + (size_t)wsel * 65536;
    const __nv_bfloat16* gWl = g_Wl + (size_t)wsel * 65536;
    int warp = tid >> 5, lane = tid & 31;
    int m0 = (warp >> 1) * 16, n0 = (warp & 1) * 128;
    int g = lane >> 2, kp = (lane & 3) * 2;

    for (int kc = 0; kc < 16; kc++) {
        // stage B chunk: Bs[n][k16] hi/lo (one row per thread)
        {
            int n = tid;
            const __nv_bfloat16* wh = gWh + n * 256 + kc * 16;
            const __nv_bfloat16* wl = gWl + n * 256 + kc * 16;
            *(uint4*)(Bh + n * SB)     = *(const uint4*)wh;
            *(uint4*)(Bh + n * SB + 8) = *(const uint4*)(wh + 8);
            *(uint4*)(Bl + n * SB)     = *(const uint4*)wl;
            *(uint4*)(Bl + n * SB + 8) = *(const uint4*)(wl + 8);
        }
        __syncthreads();

        const __nv_bfloat16* ab = Ah + (m0 + g) * SA + kc * 16 + kp;
        const __nv_bfloat16* lb = Al + (m0 + g) * SA + kc * 16 + kp;
        unsigned ah0 = *(const unsigned*)ab;
        unsigned ah2 = *(const unsigned*)(ab + 8);
        unsigned ah1 = *(const unsigned*)(ab + 8 * SA);
        unsigned ah3 = *(const unsigned*)(ab + 8 * SA + 8);
        unsigned al0 = *(const unsigned*)lb;
        unsigned al2 = *(const unsigned*)(lb + 8);
        unsigned al1 = *(const unsigned*)(lb + 8 * SA);
        unsigned al3 = *(const unsigned*)(lb + 8 * SA + 8);

#pragma unroll
        for (int nt = 0; nt < 16; nt++) {
            const __nv_bfloat16* bb = Bh + (n0 + nt * 8 + g) * SB + kp;
            const __nv_bfloat16* bl = Bl + (n0 + nt * 8 + g) * SB + kp;
            unsigned bh0 = *(const unsigned*)bb;
            unsigned bh1 = *(const unsigned*)(bb + 8);
            unsigned bl0 = *(const unsigned*)bl;
            unsigned bl1 = *(const unsigned*)(bl + 8);
            mma_bf16(acc[nt], ah0, ah1, ah2, ah3, bh0, bh1);
            mma_bf16(acc[nt], al0, al1, al2, al3, bh0, bh1);
            mma_bf16(acc[nt], ah0, ah1, ah2, ah3, bl0, bl1);
        }
        __syncthreads();
    }
}

// ---------------- weight pre-split ----------------
__global__ void k_prep_w(const float* __restrict__ W0, const float* __restrict__ W1,
                         const float* __restrict__ W2, const float* __restrict__ W3) {
    int t = blockIdx.x * 256 + threadIdx.x;
    if (t >= 262144) return;
    int w = t >> 16, n = (t >> 8) & 255, k = t & 255;
    const float* W = (w == 0) ? W0 : (w == 1) ? W1 : (w == 2) ? W2 : W3;
    float v = W[(size_t)k * HH + n];
    __nv_bfloat16 h = __float2bfloat16(v);
    g_Wh[t] = h;
    g_Wl[t] = __float2bfloat16(v - __bfloat162float(h));
}

// ---------------- utility kernels ----------------
__global__ void k_zero() {
    int idx = blockIdx.x * blockDim.x + threadIdx.x;
    const int total = NN * HH + NN;
    for (; idx < total; idx += gridDim.x * blockDim.x) {
        if (idx < NN * HH) g_agg[idx] = 0.f;
        else g_deg[idx - NN * HH] = 0.f;
    }
}
__global__ void k_deg(const int* __restrict__ ei) {
    int e = blockIdx.x * 256 + threadIdx.x;
    if (e < NE) atomicAdd(&g_deg[ei[NE + e]], 1.0f);
}
__global__ void k_scale() {
    int idx = blockIdx.x * 256 + threadIdx.x;
    if (idx < NN * HH) g_agg[idx] = g_agg[idx] / fmaxf(g_deg[idx >> 8], 1.0f);
}

// ------- node fp32 GEMM (unchanged) -------
__global__ __launch_bounds__(256) void k_sgemm(
    const float* __restrict__ A, const float* __restrict__ W,
    const float* __restrict__ bias, const float* __restrict__ addC,
    float* __restrict__ C, int M, int K, int relu)
{
    __shared__ float As[16][64];
    __shared__ float Ws[16][64];
    int tid = threadIdx.x;
    int tx = tid & 15, ty = tid >> 4;
    int row0 = blockIdx.x * 64, col0 = blockIdx.y * 64;
    float acc[4][4] = {};
    int ar = tid >> 2, ac = (tid & 3) << 2;
    int wr = tid >> 4, wc = (tid & 15) << 2;
    for (int k0 = 0; k0 < K; k0 += 16) {
        float4 av = make_float4(0.f, 0.f, 0.f, 0.f);
        if (row0 + ar < M) av = *(const float4*)(A + (size_t)(row0 + ar) * K + k0 + ac);
        As[ac + 0][ar] = av.x; As[ac + 1][ar] = av.y;
        As[ac + 2][ar] = av.z; As[ac + 3][ar] = av.w;
        *(float4*)&Ws[wr][wc] = *(const float4*)(W + (size_t)(k0 + wr) * HH + col0 + wc);
        __syncthreads();
#pragma unroll
        for (int k = 0; k < 16; k++) {
            float a[4], w[4];
#pragma unroll
            for (int i = 0; i < 4; i++) a[i] = As[k][ty * 4 + i];
#pragma unroll
            for (int j = 0; j < 4; j++) w[j] = Ws[k][tx * 4 + j];
#pragma unroll
            for (int i = 0; i < 4; i++)
#pragma unroll
                for (int j = 0; j < 4; j++) acc[i][j] += a[i] * w[j];
        }
        __syncthreads();
    }
#pragma unroll
    for (int i = 0; i < 4; i++) {
        int r = row0 + ty * 4 + i;
        if (r >= M) continue;
#pragma unroll
        for (int j = 0; j < 4; j++) {
            int c = col0 + tx * 4 + j;
            float v = acc[i][j];
            if (bias) v += bias[c];
            if (addC) v += addC[(size_t)r * HH + c];
            if (relu) v = fmaxf(v, 0.f);
            C[(size_t)r * HH + c] = v;
        }
    }
}

// ---------------- MMA edge layer 0 ----------------
__global__ __launch_bounds__(256) void k_edge0_mma(
    const int* __restrict__ ei, const float* __restrict__ eattr,
    const float* __restrict__ We0a, const float* __restrict__ be0a,
    const float* __restrict__ be0b)
{
    extern __shared__ __align__(16) unsigned char dsm[];
    __nv_bfloat16* Ah = (__nv_bfloat16*)dsm;
    __nv_bfloat16* Al = Ah + 64 * SA;
    __nv_bfloat16* Bh = Al + 64 * SA;
    __nv_bfloat16* Bl = Bh + 256 * SB;
    __shared__ float w3f[256 * 6];
    __shared__ float b0s[256], b1s[256];
    __shared__ int src_s[64], dst_s[64];

    int tid = threadIdx.x;
    int e0 = blockIdx.x * 64;
    if (tid < 64) { src_s[tid] = ei[e0 + tid]; dst_s[tid] = ei[NE + e0 + tid]; }
    b0s[tid] = be0a[tid];
    b1s[tid] = be0b[tid];
    for (int i = tid; i < 1536; i += 256)
        w3f[(i & 255) * 6 + (i >> 8)] = We0a[(size_t)(1024 + (i >> 8)) * HH + (i & 255)];
    __syncthreads();

    // build h0 tile [64 x 256] and split into Ah/Al
    {
        int m = tid >> 2, q = tid & 3;
        const float* xs = g_Xs + (size_t)src_s[m] * HH;
        const float* xd = g_Xd + (size_t)dst_s[m] * HH;
        float ear[6];
#pragma unroll
        for (int j = 0; j < 6; j++) ear[j] = eattr[(size_t)(e0 + m) * 6 + j];
        for (int k = q * 64; k < q * 64 + 64; k += 4) {
            float4 a = *(const float4*)(xs + k);
            float4 b = *(const float4*)(xd + k);
            float v[4] = {a.x + b.x, a.y + b.y, a.z + b.z, a.w + b.w};
#pragma unroll
            for (int j2 = 0; j2 < 4; j2++) {
                float t = v[j2] + b0s[k + j2];
#pragma unroll
                for (int j = 0; j < 6; j++) t += ear[j] * w3f[(k + j2) * 6 + j];
                v[j2] = fmaxf(t, 0.f);
            }
            split_store(Ah, Al, m, k, v[0], v[1]);
            split_store(Ah, Al, m, k + 2, v[2], v[3]);
        }
    }
    __syncthreads();

    float acc[16][4];
#pragma unroll
    for (int i = 0; i < 16; i++)
#pragma unroll
        for (int j = 0; j < 4; j++) acc[i][j] = 0.f;
    mma_gemm(Ah, Al, Bh, Bl, 0, acc, tid);

    // epilogue: bias, store EA1, atomic agg
    {
        int warp = tid >> 5, lane = tid & 31;
        int m0 = (warp >> 1) * 16, n0 = (warp & 1) * 128;
        int g = lane >> 2, kq = (lane & 3) * 2;
        int r0 = m0 + g, r1 = m0 + g + 8;
        size_t rb0 = (size_t)(e0 + r0) * HH, rb1 = (size_t)(e0 + r1) * HH;
        size_t ab0 = (size_t)dst_s[r0] * HH, ab1 = (size_t)dst_s[r1] * HH;
#pragma unroll
        for (int nt = 0; nt < 16; nt++) {
            int c = n0 + nt * 8 + kq;
            float2 v0 = make_float2(acc[nt][0] + b1s[c], acc[nt][1] + b1s[c + 1]);
            float2 v1 = make_float2(acc[nt][2] + b1s[c], acc[nt][3] + b1s[c + 1]);
            *(float2*)(g_EA1 + rb0 + c) = v0;
            *(float2*)(g_EA1 + rb1 + c) = v1;
            atomicAdd(&g_agg[ab0 + c],     v0.x);
            atomicAdd(&g_agg[ab0 + c + 1], v0.y);
            atomicAdd(&g_agg[ab1 + c],     v1.x);
            atomicAdd(&g_agg[ab1 + c + 1], v1.y);
        }
    }
}

// ---------------- MMA edge layer 1 + predictor ----------------
__global__ __launch_bounds__(256) void k_chain2_mma(
    const int* __restrict__ ei,
    const float* __restrict__ be1a, const float* __restrict__ be1b,
    const float* __restrict__ bp1, const float* __restrict__ Wp2,
    const float* __restrict__ bp2, float* __restrict__ out)
{
    extern __shared__ __align__(16) unsigned char dsm[];
    __nv_bfloat16* Ah = (__nv_bfloat16*)dsm;
    __nv_bfloat16* Al = Ah + 64 * SA;
    __nv_bfloat16* Bh = Al + 64 * SA;
    __nv_bfloat16* Bl = Bh + 256 * SB;
    __shared__ float b1s[256], b2s[256], bps[256], wp2s[256];
    __shared__ int src_s[64], dst_s[64];
    __shared__ float outp[64];

    int tid = threadIdx.x;
    int e0 = blockIdx.x * 64;
    if (tid < 64) {
        src_s[tid] = ei[e0 + tid];
        dst_s[tid] = ei[NE + e0 + tid];
        outp[tid] = 0.f;
    }
    b1s[tid] = be1a[tid];
    b2s[tid] = be1b[tid];
    bps[tid] = bp1[tid];
    wp2s[tid] = Wp2[tid];
    __syncthreads();

    int warp = tid >> 5, lane = tid & 31;
    int m0 = (warp >> 1) * 16, n0 = (warp & 1) * 128;
    int g = lane >> 2, kq = (lane & 3) * 2;
    int r0 = m0 + g, r1 = m0 + g + 8;

    // stage A = EA1 tile (split)
    {
        int m = tid >> 2, q = tid & 3;
        const float* er = g_EA1 + (size_t)(e0 + m) * HH;
        for (int k = q * 64; k < q * 64 + 64; k += 4) {
            float4 a = *(const float4*)(er + k);
            split_store(Ah, Al, m, k, a.x, a.y);
            split_store(Ah, Al, m, k + 2, a.z, a.w);
        }
    }
    __syncthreads();

    float acc[16][4];
#pragma unroll
    for (int i = 0; i < 16; i++)
#pragma unroll
        for (int j = 0; j < 4; j++) acc[i][j] = 0.f;

    // GEMM1: EA1 @ We1a[512:768]  (w=1); h1 = relu(. + be1a + Y1[src] + Y2[dst])
    mma_gemm(Ah, Al, Bh, Bl, 1, acc, tid);
    {
        const float* y1a = g_Y1 + (size_t)src_s[r0] * HH;
        const float* y2a = g_Y2 + (size_t)dst_s[r0] * HH;
        const float* y1b = g_Y1 + (size_t)src_s[r1] * HH;
        const float* y2b = g_Y2 + (size_t)dst_s[r1] * HH;
#pragma unroll
        for (int nt = 0; nt < 16; nt++) {
            int c = n0 + nt * 8 + kq;
            float2 p1 = *(const float2*)(y1a + c);
            float2 p2 = *(const float2*)(y2a + c);
            float2 p3 = *(const float2*)(y1b + c);
            float2 p4 = *(const float2*)(y2b + c);
            float v0 = fmaxf(acc[nt][0] + b1s[c]     + p1.x + p2.x, 0.f);
            float v1 = fmaxf(acc[nt][1] + b1s[c + 1] + p1.y + p2.y, 0.f);
            float v2 = fmaxf(acc[nt][2] + b1s[c]     + p3.x + p4.x, 0.f);
            float v3 = fmaxf(acc[nt][3] + b1s[c + 1] + p3.y + p4.y, 0.f);
            split_store(Ah, Al, r0, c, v0, v1);
            split_store(Ah, Al, r1, c, v2, v3);
            acc[nt][0] = 0.f; acc[nt][1] = 0.f; acc[nt][2] = 0.f; acc[nt][3] = 0.f;
        }
    }
    __syncthreads();

    // GEMM2: h1 @ We1b (w=2); EA2 = . + be1b + EA1 (residual from global)
    mma_gemm(Ah, Al, Bh, Bl, 2, acc, tid);
    {
        const float* era = g_EA1 + (size_t)(e0 + r0) * HH;
        const float* erb = g_EA1 + (size_t)(e0 + r1) * HH;
#pragma unroll
        for (int nt = 0; nt < 16; nt++) {
            int c = n0 + nt * 8 + kq;
            float2 q0 = *(const float2*)(era + c);
            float2 q1 = *(const float2*)(erb + c);
            float v0 = acc[nt][0] + b2s[c]     + q0.x;
            float v1 = acc[nt][1] + b2s[c + 1] + q0.y;
            float v2 = acc[nt][2] + b2s[c]     + q1.x;
            float v3 = acc[nt][3] + b2s[c + 1] + q1.y;
            split_store(Ah, Al, r0, c, v0, v1);
            split_store(Ah, Al, r1, c, v2, v3);
            acc[nt][0] = 0.f; acc[nt][1] = 0.f; acc[nt][2] = 0.f; acc[nt][3] = 0.f;
        }
    }
    __syncthreads();

    // GEMM3: EA2 @ Wp1 (w=3); leaky-relu, dot with wp2
    mma_gemm(Ah, Al, Bh, Bl, 3, acc, tid);
    {
        float p0 = 0.f, p1 = 0.f;
#pragma unroll
        for (int nt = 0; nt < 16; nt++) {
            int c = n0 + nt * 8 + kq;
            float v0 = acc[nt][0] + bps[c];
            float v1 = acc[nt][1] + bps[c + 1];
            float v2 = acc[nt][2] + bps[c];
            float v3 = acc[nt][3] + bps[c + 1];
            v0 = (v0 > 0.f) ? v0 : 0.01f * v0;
            v1 = (v1 > 0.f) ? v1 : 0.01f * v1;
            v2 = (v2 > 0.f) ? v2 : 0.01f * v2;
            v3 = (v3 > 0.f) ? v3 : 0.01f * v3;
            p0 += v0 * wp2s[c] + v1 * wp2s[c + 1];
            p1 += v2 * wp2s[c] + v3 * wp2s[c + 1];
        }
        p0 += __shfl_xor_sync(0xffffffffu, p0, 1);
        p0 += __shfl_xor_sync(0xffffffffu, p0, 2);
        p1 += __shfl_xor_sync(0xffffffffu, p1, 1);
        p1 += __shfl_xor_sync(0xffffffffu, p1, 2);
        if ((lane & 3) == 0) {
            atomicAdd(&outp[r0], p0);
            atomicAdd(&outp[r1], p1);
        }
    }
    __syncthreads();
    if (tid < 64) out[e0 + tid] = outp[tid] + bp2[0];
}

// ---------------- host launcher ----------------
extern "C" void kernel_launch(void* const* d_in, const int* in_sizes, int n_in,
                              void* d_out, int out_size)
{
    (void)in_sizes; (void)n_in; (void)out_size;
    const float* x    = (const float*)d_in[0];
    const int*   ei   = (const int*)  d_in[1];
    const float* ea   = (const float*)d_in[2];
    const float* We0a = (const float*)d_in[3];
    const float* be0a = (const float*)d_in[4];
    const float* We0b = (const float*)d_in[5];
    const float* be0b = (const float*)d_in[6];
    const float* Wn0a = (const float*)d_in[7];
    const float* bn0a = (const float*)d_in[8];
    const float* Wn0b = (const float*)d_in[9];
    const float* bn0b = (const float*)d_in[10];
    const float* We1a = (const float*)d_in[11];
    const float* be1a = (const float*)d_in[12];
    const float* We1b = (const float*)d_in[13];
    const float* be1b = (const float*)d_in[14];
    const float* Wp1  = (const float*)d_in[19];
    const float* bp1  = (const float*)d_in[20];
    const float* Wp2  = (const float*)d_in[21];
    const float* bp2  = (const float*)d_in[22];
    float* out = (float*)d_out;

    const int DSM = (2 * 64 * SA + 2 * 256 * SB) * 2;  // 92160 bytes
    cudaFuncSetAttribute(k_edge0_mma,  cudaFuncAttributeMaxDynamicSharedMemorySize, DSM);
    cudaFuncSetAttribute(k_chain2_mma, cudaFuncAttributeMaxDynamicSharedMemorySize, DSM);

    void *p_Xs, *p_Xd, *p_agg, *p_P, *p_x1h, *p_x1, *p_Y1, *p_Y2;
    cudaGetSymbolAddress(&p_Xs,  g_Xs);
    cudaGetSymbolAddress(&p_Xd,  g_Xd);
    cudaGetSymbolAddress(&p_agg, g_agg);
    cudaGetSymbolAddress(&p_P,   g_P);
    cudaGetSymbolAddress(&p_x1h, g_x1h);
    cudaGetSymbolAddress(&p_x1,  g_x1);
    cudaGetSymbolAddress(&p_Y1,  g_Y1);
    cudaGetSymbolAddress(&p_Y2,  g_Y2);

    dim3 gN((NN + 63) / 64, 4);

    // pre-split weights: w0=We0b, w1=We1a[512:768], w2=We1b, w3=Wp1
    k_prep_w<<<1024, 256>>>(We0b, We1a + 512 * HH, We1b, Wp1);

    k_zero<<<2048, 256>>>();
    k_deg<<<NE / 256, 256>>>(ei);

    // layer-0 edge precompute: Xs = x@We0a[0:512], Xd = x@We0a[512:1024]
    k_sgemm<<<gN, 256>>>(x, We0a,            nullptr, nullptr, (float*)p_Xs, NN, FIN, 0);
    k_sgemm<<<gN, 256>>>(x, We0a + 512 * HH, nullptr, nullptr, (float*)p_Xd, NN, FIN, 0);

    // fused edge layer 0 (HMMA) -> EA1, agg
    k_edge0_mma<<<NE / 64, 256, DSM>>>(ei, ea, We0a, be0a, be0b);
    k_scale<<<(NN * HH + 255) / 256, 256>>>();

    // node MLP 0: x1 = relu(x@Wn0a_top + agg@Wn0a_bot + bn0a) @ Wn0b + bn0b
    k_sgemm<<<gN, 256>>>(x, Wn0a, nullptr, nullptr, (float*)p_P, NN, FIN, 0);
    k_sgemm<<<gN, 256>>>((const float*)p_agg, Wn0a + 512 * HH, bn0a, (const float*)p_P,
                         (float*)p_x1h, NN, HH, 1);
    k_sgemm<<<gN, 256>>>((const float*)p_x1h, Wn0b, bn0b, nullptr, (float*)p_x1, NN, HH, 0);

    // layer-1 edge precompute: Y1 = x1@We1a[0:256], Y2 = x1@We1a[256:512]
    k_sgemm<<<gN, 256>>>((const float*)p_x1, We1a,            nullptr, nullptr, (float*)p_Y1, NN, HH, 0);
    k_sgemm<<<gN, 256>>>((const float*)p_x1, We1a + 256 * HH, nullptr, nullptr, (float*)p_Y2, NN, HH, 0);

    // fused edge layer 1 + residual + predictor (HMMA)
    k_chain2_mma<<<NE / 64, 256, DSM>>>(ei, be1a, be1b, bp1, Wp2, bp2, out);
}

// round 11
// speedup vs baseline: 1.3330x; 1.0566x over previous
#include <cuda_runtime.h>
#include <cuda_bf16.h>
#include <cstdint>
#include <cstddef>

#define NN 10000
#define NE 320000
#define FIN 512
#define HH 256
#define SA 264   // edge A smem stride (bf16): 528B/row
#define SB 24    // B smem stride (bf16): 48B/row
#define SAN 20   // node A chunk smem stride

// ---------------- scratch ----------------
__device__ float g_Xs[NN * HH];
__device__ float g_Xd[NN * HH];
__device__ float g_agg[NN * HH];
__device__ float g_deg[NN];
__device__ float g_P[NN * HH];
__device__ float g_x1h[NN * HH];
__device__ float g_x1[NN * HH];
__device__ float g_Y1[NN * HH];
__device__ float g_Y2[NN * HH];
__device__ float g_EA1[(size_t)NE * HH];
// pre-split weight pool, layout [n][k] (k contiguous), hi & lo
// offsets: 0:We0b 65536:We1a[512:768] 131072:We1b 196608:Wp1
//          262144:We0a[0:512] 393216:We0a[512:1024] 524288:Wn0a[0:512]
//          655360:Wn0a[512:768] 720896:Wn0b 786432:We1a[0:256] 851968:We1a[256:512]
__device__ __align__(128) __nv_bfloat16 g_Wh[917504];
__device__ __align__(128) __nv_bfloat16 g_Wl[917504];

// ---------------- helpers ----------------
__device__ __forceinline__ void mma_bf16(float* c, unsigned a0, unsigned a1, unsigned a2,
                                         unsigned a3, unsigned b0, unsigned b1) {
    asm volatile(
        "mma.sync.aligned.m16n8k16.row.col.f32.bf16.bf16.f32 "
        "{%0,%1,%2,%3}, {%4,%5,%6,%7}, {%8,%9}, {%0,%1,%2,%3};"
        : "+f"(c[0]), "+f"(c[1]), "+f"(c[2]), "+f"(c[3])
        : "r"(a0), "r"(a1), "r"(a2), "r"(a3), "r"(b0), "r"(b1));
}
__device__ __forceinline__ void split2(float v0, float v1, unsigned& hp, unsigned& lp) {
    __nv_bfloat16 h0 = __float2bfloat16(v0), h1 = __float2bfloat16(v1);
    __nv_bfloat16 l0 = __float2bfloat16(v0 - __bfloat162float(h0));
    __nv_bfloat16 l1 = __float2bfloat16(v1 - __bfloat162float(h1));
    hp = (unsigned)__bfloat16_as_ushort(h0) | ((unsigned)__bfloat16_as_ushort(h1) << 16);
    lp = (unsigned)__bfloat16_as_ushort(l0) | ((unsigned)__bfloat16_as_ushort(l1) << 16);
}
__device__ __forceinline__ void split_storeS(__nv_bfloat16* Ah, __nv_bfloat16* Al, int stride,
                                             int m, int k, float v0, float v1) {
    unsigned hp, lp;
    split2(v0, v1, hp, lp);
    *(unsigned*)(Ah + m * stride + k) = hp;
    *(unsigned*)(Al + m * stride + k) = lp;
}
__device__ __forceinline__ void red2(float* p, float x, float y) {
    asm volatile("red.global.add.v2.f32 [%0], {%1,%2};" :: "l"(p), "f"(x), "f"(y) : "memory");
}

// ---- edge warp-mma GEMM with register-prefetched B ----
// acc[16][4] += A(64x256 smem hi/lo) @ W(256x256, presplit [n][256] at gWh/gWl)
__device__ __forceinline__ void mma_gemm(
    const __nv_bfloat16* Ah, const __nv_bfloat16* Al,
    __nv_bfloat16* Bh, __nv_bfloat16* Bl,
    const __nv_bfloat16* gWh, const __nv_bfloat16* gWl,
    float (&acc)[16][4], int tid)
{
    int warp = tid >> 5, lane = tid & 31;
    int m0 = (warp >> 1) * 16, n0 = (warp & 1) * 128;
    int g = lane >> 2, kp = (lane & 3) * 2;
    const __nv_bfloat16* wh = gWh + tid * 256;
    const __nv_bfloat16* wl = gWl + tid * 256;

    uint4 rh0 = *(const uint4*)(wh);
    uint4 rh1 = *(const uint4*)(wh + 8);
    uint4 rl0 = *(const uint4*)(wl);
    uint4 rl1 = *(const uint4*)(wl + 8);

    for (int kc = 0; kc < 16; kc++) {
        *(uint4*)(Bh + tid * SB)     = rh0;
        *(uint4*)(Bh + tid * SB + 8) = rh1;
        *(uint4*)(Bl + tid * SB)     = rl0;
        *(uint4*)(Bl + tid * SB + 8) = rl1;
        __syncthreads();
        if (kc + 1 < 16) {
            rh0 = *(const uint4*)(wh + (kc + 1) * 16);
            rh1 = *(const uint4*)(wh + (kc + 1) * 16 + 8);
            rl0 = *(const uint4*)(wl + (kc + 1) * 16);
            rl1 = *(const uint4*)(wl + (kc + 1) * 16 + 8);
        }
        const __nv_bfloat16* ab = Ah + (m0 + g) * SA + kc * 16 + kp;
        const __nv_bfloat16* lb = Al + (m0 + g) * SA + kc * 16 + kp;
        unsigned ah0 = *(const unsigned*)ab;
        unsigned ah2 = *(const unsigned*)(ab + 8);
        unsigned ah1 = *(const unsigned*)(ab + 8 * SA);
        unsigned ah3 = *(const unsigned*)(ab + 8 * SA + 8);
        unsigned al0 = *(const unsigned*)lb;
        unsigned al2 = *(const unsigned*)(lb + 8);
        unsigned al1 = *(const unsigned*)(lb + 8 * SA);
        unsigned al3 = *(const unsigned*)(lb + 8 * SA + 8);
#pragma unroll
        for (int nt = 0; nt < 16; nt++) {
            const __nv_bfloat16* bb = Bh + (n0 + nt * 8 + g) * SB + kp;
            const __nv_bfloat16* bl = Bl + (n0 + nt * 8 + g) * SB + kp;
            unsigned bh0 = *(const unsigned*)bb;
            unsigned bh1 = *(const unsigned*)(bb + 8);
            unsigned bl0 = *(const unsigned*)bl;
            unsigned bl1 = *(const unsigned*)(bl + 8);
            mma_bf16(acc[nt], ah0, ah1, ah2, ah3, bh0, bh1);
            mma_bf16(acc[nt], al0, al1, al2, al3, bh0, bh1);
            mma_bf16(acc[nt], ah0, ah1, ah2, ah3, bl0, bl1);
        }
        __syncthreads();
    }
}

// ---------------- weight pre-split (one weight per launch) ----------------
__global__ void k_prep1(const float* __restrict__ W, int K, int dstoff) {
    int t = blockIdx.x * 256 + threadIdx.x;
    if (t >= 256 * K) return;
    int n = t / K, k = t - n * K;
    float v = W[(size_t)k * HH + n];
    __nv_bfloat16 h = __float2bfloat16(v);
    g_Wh[dstoff + t] = h;
    g_Wl[dstoff + t] = __float2bfloat16(v - __bfloat162float(h));
}

// ---------------- utility kernels ----------------
__global__ void k_zero() {
    int idx = blockIdx.x * blockDim.x + threadIdx.x;
    const int total = NN * HH + NN;
    for (; idx < total; idx += gridDim.x * blockDim.x) {
        if (idx < NN * HH) g_agg[idx] = 0.f;
        else g_deg[idx - NN * HH] = 0.f;
    }
}
__global__ void k_deg(const int* __restrict__ ei) {
    int e = blockIdx.x * 256 + threadIdx.x;
    if (e < NE) atomicAdd(&g_deg[ei[NE + e]], 1.0f);
}
__global__ void k_scale() {
    int idx = blockIdx.x * 256 + threadIdx.x;
    if (idx < NN * HH) g_agg[idx] = g_agg[idx] / fmaxf(g_deg[idx >> 8], 1.0f);
}

// ------- node HMMA GEMM: C[M,256] = act(A[M,K] @ W + bias + addC) -------
__global__ __launch_bounds__(256) void k_hgemm(
    const float* __restrict__ A, int M, int K,
    const __nv_bfloat16* __restrict__ gWh, const __nv_bfloat16* __restrict__ gWl,
    const float* __restrict__ bias, const float* __restrict__ addC,
    float* __restrict__ C, int relu)
{
    __shared__ __nv_bfloat16 Ah[64 * SAN], Al[64 * SAN];
    __shared__ __nv_bfloat16 Bh[256 * SB], Bl[256 * SB];
    int tid = threadIdx.x;
    int row0 = blockIdx.x * 64;
    int warp = tid >> 5, lane = tid & 31;
    int m0 = (warp >> 1) * 16, n0 = (warp & 1) * 128;
    int g = lane >> 2, kq = (lane & 3) * 2;
    float acc[16][4];
#pragma unroll
    for (int i = 0; i < 16; i++)
#pragma unroll
        for (int j = 0; j < 4; j++) acc[i][j] = 0.f;

    int ar = tid >> 2, ac = (tid & 3) * 4;
    int arow = row0 + ar;
    if (arow >= M) arow = M - 1;
    const float* Arow = A + (size_t)arow * K;
    const __nv_bfloat16* wh = gWh + (size_t)tid * K;
    const __nv_bfloat16* wl = gWl + (size_t)tid * K;

    float4 av = *(const float4*)(Arow + ac);
    uint4 rh0 = *(const uint4*)(wh);
    uint4 rh1 = *(const uint4*)(wh + 8);
    uint4 rl0 = *(const uint4*)(wl);
    uint4 rl1 = *(const uint4*)(wl + 8);

    int nch = K >> 4;
    for (int kc = 0; kc < nch; kc++) {
        split_storeS(Ah, Al, SAN, ar, ac, av.x, av.y);
        split_storeS(Ah, Al, SAN, ar, ac + 2, av.z, av.w);
        *(uint4*)(Bh + tid * SB)     = rh0;
        *(uint4*)(Bh + tid * SB + 8) = rh1;
        *(uint4*)(Bl + tid * SB)     = rl0;
        *(uint4*)(Bl + tid * SB + 8) = rl1;
        __syncthreads();
        if (kc + 1 < nch) {
            av = *(const float4*)(Arow + (kc + 1) * 16 + ac);
            rh0 = *(const uint4*)(wh + (kc + 1) * 16);
            rh1 = *(const uint4*)(wh + (kc + 1) * 16 + 8);
            rl0 = *(const uint4*)(wl + (kc + 1) * 16);
            rl1 = *(const uint4*)(wl + (kc + 1) * 16 + 8);
        }
        const __nv_bfloat16* ab = Ah + (m0 + g) * SAN + kq;
        const __nv_bfloat16* lb = Al + (m0 + g) * SAN + kq;
        unsigned ah0 = *(const unsigned*)ab;
        unsigned ah2 = *(const unsigned*)(ab + 8);
        unsigned ah1 = *(const unsigned*)(ab + 8 * SAN);
        unsigned ah3 = *(const unsigned*)(ab + 8 * SAN + 8);
        unsigned al0 = *(const unsigned*)lb;
        unsigned al2 = *(const unsigned*)(lb + 8);
        unsigned al1 = *(const unsigned*)(lb + 8 * SAN);
        unsigned al3 = *(const unsigned*)(lb + 8 * SAN + 8);
#pragma unroll
        for (int nt = 0; nt < 16; nt++) {
            const __nv_bfloat16* bb = Bh + (n0 + nt * 8 + g) * SB + kq;
            const __nv_bfloat16* bl = Bl + (n0 + nt * 8 + g) * SB + kq;
            unsigned bh0 = *(const unsigned*)bb;
            unsigned bh1 = *(const unsigned*)(bb + 8);
            unsigned bl0 = *(const unsigned*)bl;
            unsigned bl1 = *(const unsigned*)(bl + 8);
            mma_bf16(acc[nt], ah0, ah1, ah2, ah3, bh0, bh1);
            mma_bf16(acc[nt], al0, al1, al2, al3, bh0, bh1);
            mma_bf16(acc[nt], ah0, ah1, ah2, ah3, bl0, bl1);
        }
        __syncthreads();
    }

    int r0 = row0 + m0 + g, r1 = r0 + 8;
#pragma unroll
    for (int nt = 0; nt < 16; nt++) {
        int c = n0 + nt * 8 + kq;
        float b0 = bias ? bias[c] : 0.f, b1 = bias ? bias[c + 1] : 0.f;
        if (r0 < M) {
            float v0 = acc[nt][0] + b0, v1 = acc[nt][1] + b1;
            if (addC) { v0 += addC[(size_t)r0 * HH + c]; v1 += addC[(size_t)r0 * HH + c + 1]; }
            if (relu) { v0 = fmaxf(v0, 0.f); v1 = fmaxf(v1, 0.f); }
            *(float2*)(C + (size_t)r0 * HH + c) = make_float2(v0, v1);
        }
        if (r1 < M) {
            float v2 = acc[nt][2] + b0, v3 = acc[nt][3] + b1;
            if (addC) { v2 += addC[(size_t)r1 * HH + c]; v3 += addC[(size_t)r1 * HH + c + 1]; }
            if (relu) { v2 = fmaxf(v2, 0.f); v3 = fmaxf(v3, 0.f); }
            *(float2*)(C + (size_t)r1 * HH + c) = make_float2(v2, v3);
        }
    }
}

// ---------------- MMA edge layer 0 ----------------
__global__ __launch_bounds__(256) void k_edge0_mma(
    const int* __restrict__ ei, const float* __restrict__ eattr,
    const float* __restrict__ We0a, const float* __restrict__ be0a,
    const float* __restrict__ be0b)
{
    extern __shared__ __align__(16) unsigned char dsm[];
    __nv_bfloat16* Ah = (__nv_bfloat16*)dsm;
    __nv_bfloat16* Al = Ah + 64 * SA;
    __nv_bfloat16* Bh = Al + 64 * SA;
    __nv_bfloat16* Bl = Bh + 256 * SB;
    __shared__ float w3f[256 * 6];
    __shared__ float b0s[256], b1s[256];
    __shared__ int src_s[64], dst_s[64];

    int tid = threadIdx.x;
    int e0 = blockIdx.x * 64;
    if (tid < 64) { src_s[tid] = ei[e0 + tid]; dst_s[tid] = ei[NE + e0 + tid]; }
    b0s[tid] = be0a[tid];
    b1s[tid] = be0b[tid];
    for (int i = tid; i < 1536; i += 256)
        w3f[(i & 255) * 6 + (i >> 8)] = We0a[(size_t)(1024 + (i >> 8)) * HH + (i & 255)];
    __syncthreads();

    {
        int m = tid >> 2, q = tid & 3;
        const float* xs = g_Xs + (size_t)src_s[m] * HH;
        const float* xd = g_Xd + (size_t)dst_s[m] * HH;
        float ear[6];
#pragma unroll
        for (int j = 0; j < 6; j++) ear[j] = eattr[(size_t)(e0 + m) * 6 + j];
        for (int k = q * 64; k < q * 64 + 64; k += 4) {
            float4 a = *(const float4*)(xs + k);
            float4 b = *(const float4*)(xd + k);
            float v[4] = {a.x + b.x, a.y + b.y, a.z + b.z, a.w + b.w};
#pragma unroll
            for (int j2 = 0; j2 < 4; j2++) {
                float t = v[j2] + b0s[k + j2];
#pragma unroll
                for (int j = 0; j < 6; j++) t += ear[j] * w3f[(k + j2) * 6 + j];
                v[j2] = fmaxf(t, 0.f);
            }
            split_storeS(Ah, Al, SA, m, k, v[0], v[1]);
            split_storeS(Ah, Al, SA, m, k + 2, v[2], v[3]);
        }
    }
    __syncthreads();

    float acc[16][4];
#pragma unroll
    for (int i = 0; i < 16; i++)
#pragma unroll
        for (int j = 0; j < 4; j++) acc[i][j] = 0.f;
    mma_gemm(Ah, Al, Bh, Bl, g_Wh, g_Wl, acc, tid);

    {
        int warp = tid >> 5, lane = tid & 31;
        int m0 = (warp >> 1) * 16, n0 = (warp & 1) * 128;
        int g = lane >> 2, kq = (lane & 3) * 2;
        int r0 = m0 + g, r1 = m0 + g + 8;
        size_t rb0 = (size_t)(e0 + r0) * HH, rb1 = (size_t)(e0 + r1) * HH;
        size_t ab0 = (size_t)dst_s[r0] * HH, ab1 = (size_t)dst_s[r1] * HH;
#pragma unroll
        for (int nt = 0; nt < 16; nt++) {
            int c = n0 + nt * 8 + kq;
            float2 v0 = make_float2(acc[nt][0] + b1s[c], acc[nt][1] + b1s[c + 1]);
            float2 v1 = make_float2(acc[nt][2] + b1s[c], acc[nt][3] + b1s[c + 1]);
            *(float2*)(g_EA1 + rb0 + c) = v0;
            *(float2*)(g_EA1 + rb1 + c) = v1;
            red2(g_agg + ab0 + c, v0.x, v0.y);
            red2(g_agg + ab1 + c, v1.x, v1.y);
        }
    }
}

// ---------------- MMA edge layer 1 + predictor ----------------
__global__ __launch_bounds__(256) void k_chain2_mma(
    const int* __restrict__ ei,
    const float* __restrict__ be1a, const float* __restrict__ be1b,
    const float* __restrict__ bp1, const float* __restrict__ Wp2,
    const float* __restrict__ bp2, float* __restrict__ out)
{
    extern __shared__ __align__(16) unsigned char dsm[];
    __nv_bfloat16* Ah = (__nv_bfloat16*)dsm;
    __nv_bfloat16* Al = Ah + 64 * SA;
    __nv_bfloat16* Bh = Al + 64 * SA;
    __nv_bfloat16* Bl = Bh + 256 * SB;
    __shared__ float b1s[256], b2s[256], bps[256], wp2s[256];
    __shared__ int src_s[64], dst_s[64];
    __shared__ float outp[64];

    int tid = threadIdx.x;
    int e0 = blockIdx.x * 64;
    if (tid < 64) {
        src_s[tid] = ei[e0 + tid];
        dst_s[tid] = ei[NE + e0 + tid];
        outp[tid] = 0.f;
    }
    b1s[tid] = be1a[tid];
    b2s[tid] = be1b[tid];
    bps[tid] = bp1[tid];
    wp2s[tid] = Wp2[tid];
    __syncthreads();

    int warp = tid >> 5, lane = tid & 31;
    int m0 = (warp >> 1) * 16, n0 = (warp & 1) * 128;
    int g = lane >> 2, kq = (lane & 3) * 2;
    int r0 = m0 + g, r1 = m0 + g + 8;

    {
        int m = tid >> 2, q = tid & 3;
        const float* er = g_EA1 + (size_t)(e0 + m) * HH;
        for (int k = q * 64; k < q * 64 + 64; k += 4) {
            float4 a = *(const float4*)(er + k);
            split_storeS(Ah, Al, SA, m, k, a.x, a.y);
            split_storeS(Ah, Al, SA, m, k + 2, a.z, a.w);
        }
    }
    __syncthreads();

    float acc[16][4];
#pragma unroll
    for (int i = 0; i < 16; i++)
#pragma unroll
        for (int j = 0; j < 4; j++) acc[i][j] = 0.f;

    // GEMM1: EA1 @ We1a[512:768]; h1 = relu(. + be1a + Y1[src] + Y2[dst])
    mma_gemm(Ah, Al, Bh, Bl, g_Wh + 65536, g_Wl + 65536, acc, tid);
    {
        const float* y1a = g_Y1 + (size_t)src_s[r0] * HH;
        const float* y2a = g_Y2 + (size_t)dst_s[r0] * HH;
        const float* y1b = g_Y1 + (size_t)src_s[r1] * HH;
        const float* y2b = g_Y2 + (size_t)dst_s[r1] * HH;
#pragma unroll
        for (int nt = 0; nt < 16; nt++) {
            int c = n0 + nt * 8 + kq;
            float2 p1 = *(const float2*)(y1a + c);
            float2 p2 = *(const float2*)(y2a + c);
            float2 p3 = *(const float2*)(y1b + c);
            float2 p4 = *(const float2*)(y2b + c);
            float v0 = fmaxf(acc[nt][0] + b1s[c]     + p1.x + p2.x, 0.f);
            float v1 = fmaxf(acc[nt][1] + b1s[c + 1] + p1.y + p2.y, 0.f);
            float v2 = fmaxf(acc[nt][2] + b1s[c]     + p3.x + p4.x, 0.f);
            float v3 = fmaxf(acc[nt][3] + b1s[c + 1] + p3.y + p4.y, 0.f);
            split_storeS(Ah, Al, SA, r0, c, v0, v1);
            split_storeS(Ah, Al, SA, r1, c, v2, v3);
            acc[nt][0] = 0.f; acc[nt][1] = 0.f; acc[nt][2] = 0.f; acc[nt][3] = 0.f;
        }
    }
    __syncthreads();

    // GEMM2: h1 @ We1b; EA2 = . + be1b + EA1
    mma_gemm(Ah, Al, Bh, Bl, g_Wh + 131072, g_Wl + 131072, acc, tid);
    {
        const float* era = g_EA1 + (size_t)(e0 + r0) * HH;
        const float* erb = g_EA1 + (size_t)(e0 + r1) * HH;
#pragma unroll
        for (int nt = 0; nt < 16; nt++) {
            int c = n0 + nt * 8 + kq;
            float2 q0 = *(const float2*)(era + c);
            float2 q1 = *(const float2*)(erb + c);
            float v0 = acc[nt][0] + b2s[c]     + q0.x;
            float v1 = acc[nt][1] + b2s[c + 1] + q0.y;
            float v2 = acc[nt][2] + b2s[c]     + q1.x;
            float v3 = acc[nt][3] + b2s[c + 1] + q1.y;
            split_storeS(Ah, Al, SA, r0, c, v0, v1);
            split_storeS(Ah, Al, SA, r1, c, v2, v3);
            acc[nt][0] = 0.f; acc[nt][1] = 0.f; acc[nt][2] = 0.f; acc[nt][3] = 0.f;
        }
    }
    __syncthreads();

    // GEMM3: EA2 @ Wp1; leaky-relu, dot wp2
    mma_gemm(Ah, Al, Bh, Bl, g_Wh + 196608, g_Wl + 196608, acc, tid);
    {
        float p0 = 0.f, p1 = 0.f;
#pragma unroll
        for (int nt = 0; nt < 16; nt++) {
            int c = n0 + nt * 8 + kq;
            float v0 = acc[nt][0] + bps[c];
            float v1 = acc[nt][1] + bps[c + 1];
            float v2 = acc[nt][2] + bps[c];
            float v3 = acc[nt][3] + bps[c + 1];
            v0 = (v0 > 0.f) ? v0 : 0.01f * v0;
            v1 = (v1 > 0.f) ? v1 : 0.01f * v1;
            v2 = (v2 > 0.f) ? v2 : 0.01f * v2;
            v3 = (v3 > 0.f) ? v3 : 0.01f * v3;
            p0 += v0 * wp2s[c] + v1 * wp2s[c + 1];
            p1 += v2 * wp2s[c] + v3 * wp2s[c + 1];
        }
        p0 += __shfl_xor_sync(0xffffffffu, p0, 1);
        p0 += __shfl_xor_sync(0xffffffffu, p0, 2);
        p1 += __shfl_xor_sync(0xffffffffu, p1, 1);
        p1 += __shfl_xor_sync(0xffffffffu, p1, 2);
        if ((lane & 3) == 0) {
            atomicAdd(&outp[r0], p0);
            atomicAdd(&outp[r1], p1);
        }
    }
    __syncthreads();
    if (tid < 64) out[e0 + tid] = outp[tid] + bp2[0];
}

// ---------------- host launcher ----------------
extern "C" void kernel_launch(void* const* d_in, const int* in_sizes, int n_in,
                              void* d_out, int out_size)
{
    (void)in_sizes; (void)n_in; (void)out_size;
    const float* x    = (const float*)d_in[0];
    const int*   ei   = (const int*)  d_in[1];
    const float* ea   = (const float*)d_in[2];
    const float* We0a = (const float*)d_in[3];
    const float* be0a = (const float*)d_in[4];
    const float* We0b = (const float*)d_in[5];
    const float* be0b = (const float*)d_in[6];
    const float* Wn0a = (const float*)d_in[7];
    const float* bn0a = (const float*)d_in[8];
    const float* Wn0b = (const float*)d_in[9];
    const float* bn0b = (const float*)d_in[10];
    const float* We1a = (const float*)d_in[11];
    const float* be1a = (const float*)d_in[12];
    const float* We1b = (const float*)d_in[13];
    const float* be1b = (const float*)d_in[14];
    const float* Wp1  = (const float*)d_in[19];
    const float* bp1  = (const float*)d_in[20];
    const float* Wp2  = (const float*)d_in[21];
    const float* bp2  = (const float*)d_in[22];
    float* out = (float*)d_out;

    const int DSM = (2 * 64 * SA + 2 * 256 * SB) * 2;  // 92160 bytes
    cudaFuncSetAttribute(k_edge0_mma,  cudaFuncAttributeMaxDynamicSharedMemorySize, DSM);
    cudaFuncSetAttribute(k_chain2_mma, cudaFuncAttributeMaxDynamicSharedMemorySize, DSM);

    void *p_Xs, *p_Xd, *p_agg, *p_P, *p_x1h, *p_x1, *p_Y1, *p_Y2, *p_Wh, *p_Wl;
    cudaGetSymbolAddress(&p_Xs,  g_Xs);
    cudaGetSymbolAddress(&p_Xd,  g_Xd);
    cudaGetSymbolAddress(&p_agg, g_agg);
    cudaGetSymbolAddress(&p_P,   g_P);
    cudaGetSymbolAddress(&p_x1h, g_x1h);
    cudaGetSymbolAddress(&p_x1,  g_x1);
    cudaGetSymbolAddress(&p_Y1,  g_Y1);
    cudaGetSymbolAddress(&p_Y2,  g_Y2);
    cudaGetSymbolAddress(&p_Wh,  g_Wh);
    cudaGetSymbolAddress(&p_Wl,  g_Wl);
    const __nv_bfloat16* Wh = (const __nv_bfloat16*)p_Wh;
    const __nv_bfloat16* Wl = (const __nv_bfloat16*)p_Wl;

    // pre-split all weights into [n][k] bf16 hi/lo pool
    k_prep1<<<256, 256>>>(We0b,            256, 0);
    k_prep1<<<256, 256>>>(We1a + 512 * HH, 256, 65536);
    k_prep1<<<256, 256>>>(We1b,            256, 131072);
    k_prep1<<<256, 256>>>(Wp1,             256, 196608);
    k_prep1<<<512, 256>>>(We0a,            512, 262144);
    k_prep1<<<512, 256>>>(We0a + 512 * HH, 512, 393216);
    k_prep1<<<512, 256>>>(Wn0a,            512, 524288);
    k_prep1<<<256, 256>>>(Wn0a + 512 * HH, 256, 655360);
    k_prep1<<<256, 256>>>(Wn0b,            256, 720896);
    k_prep1<<<256, 256>>>(We1a,            256, 786432);
    k_prep1<<<256, 256>>>(We1a + 256 * HH, 256, 851968);

    k_zero<<<2048, 256>>>();
    k_deg<<<NE / 256, 256>>>(ei);

    const int gM = (NN + 63) / 64;

    // layer-0 edge precompute: Xs = x@We0a[0:512], Xd = x@We0a[512:1024]
    k_hgemm<<<gM, 256>>>(x, NN, FIN, Wh + 262144, Wl + 262144, nullptr, nullptr, (float*)p_Xs, 0);
    k_hgemm<<<gM, 256>>>(x, NN, FIN, Wh + 393216, Wl + 393216, nullptr, nullptr, (float*)p_Xd, 0);

    // fused edge layer 0 (HMMA) -> EA1, agg
    k_edge0_mma<<<NE / 64, 256, DSM>>>(ei, ea, We0a, be0a, be0b);
    k_scale<<<(NN * HH + 255) / 256, 256>>>();

    // node MLP 0: x1 = relu(x@Wn0a_top + agg@Wn0a_bot + bn0a) @ Wn0b + bn0b
    k_hgemm<<<gM, 256>>>(x, NN, FIN, Wh + 524288, Wl + 524288, nullptr, nullptr, (float*)p_P, 0);
    k_hgemm<<<gM, 256>>>((const float*)p_agg, NN, HH, Wh + 655360, Wl + 655360, bn0a,
                         (const float*)p_P, (float*)p_x1h, 1);
    k_hgemm<<<gM, 256>>>((const float*)p_x1h, NN, HH, Wh + 720896, Wl + 720896, bn0b,
                         nullptr, (float*)p_x1, 0);

    // layer-1 edge precompute: Y1 = x1@We1a[0:256], Y2 = x1@We1a[256:512]
    k_hgemm<<<gM, 256>>>((const float*)p_x1, NN, HH, Wh + 786432, Wl + 786432, nullptr, nullptr, (float*)p_Y1, 0);
    k_hgemm<<<gM, 256>>>((const float*)p_x1, NN, HH, Wh + 851968, Wl + 851968, nullptr, nullptr, (float*)p_Y2, 0);

    // fused edge layer 1 + residual + predictor (HMMA)
    k_chain2_mma<<<NE / 64, 256, DSM>>>(ei, be1a, be1b, bp1, Wp2, bp2, out);
}

// round 12
// speedup vs baseline: 2.0429x; 1.5326x over previous
#include <cuda_runtime.h>
#include <cuda_fp16.h>
#include <cstdint>
#include <cstddef>

#define NN 10000
#define NE 320000
#define FIN 512
#define HH 256
#define SA 264   // edge A smem stride (fp16 elems): 528B/row
#define SB 24    // B smem stride (fp16 elems): 48B/row
#define SAN 20   // node A chunk smem stride

// ---------------- scratch ----------------
__device__ float g_Xs[NN * HH];
__device__ float g_Xd[NN * HH];
__device__ float g_agg[NN * HH];
__device__ float g_deg[NN];
__device__ float g_P[NN * HH];
__device__ float g_x1h[NN * HH];
__device__ float g_x1[NN * HH];
__device__ float g_Y1[NN * HH];
__device__ float g_Y2[NN * HH];
__device__ float g_EA1[(size_t)NE * HH];
// fp16 weight pool, layout [n][k] (k contiguous)
// offsets: 0:We0b 65536:We1a[512:768] 131072:We1b 196608:Wp1
//          262144:We0a[0:512] 393216:We0a[512:1024] 524288:Wn0a[0:512]
//          655360:Wn0a[512:768] 720896:Wn0b 786432:We1a[0:256] 851968:We1a[256:512]
__device__ __align__(128) __half g_Wh[917504];

// ---------------- helpers ----------------
__device__ __forceinline__ void mma_f16(float* c, unsigned a0, unsigned a1, unsigned a2,
                                        unsigned a3, unsigned b0, unsigned b1) {
    asm volatile(
        "mma.sync.aligned.m16n8k16.row.col.f32.f16.f16.f32 "
        "{%0,%1,%2,%3}, {%4,%5,%6,%7}, {%8,%9}, {%0,%1,%2,%3};"
        : "+f"(c[0]), "+f"(c[1]), "+f"(c[2]), "+f"(c[3])
        : "r"(a0), "r"(a1), "r"(a2), "r"(a3), "r"(b0), "r"(b1));
}
__device__ __forceinline__ void split2(float v0, float v1, unsigned& hp, unsigned& lp) {
    __half h0 = __float2half_rn(v0), h1 = __float2half_rn(v1);
    __half l0 = __float2half_rn(v0 - __half2float(h0));
    __half l1 = __float2half_rn(v1 - __half2float(h1));
    hp = (unsigned)__half_as_ushort(h0) | ((unsigned)__half_as_ushort(h1) << 16);
    lp = (unsigned)__half_as_ushort(l0) | ((unsigned)__half_as_ushort(l1) << 16);
}
__device__ __forceinline__ void split_storeS(__half* Ah, __half* Al, int stride,
                                             int m, int k, float v0, float v1) {
    unsigned hp, lp;
    split2(v0, v1, hp, lp);
    *(unsigned*)(Ah + m * stride + k) = hp;
    *(unsigned*)(Al + m * stride + k) = lp;
}
__device__ __forceinline__ void red2(float* p, float x, float y) {
    asm volatile("red.global.add.v2.f32 [%0], {%1,%2};" :: "l"(p), "f"(x), "f"(y) : "memory");
}

// ---- edge warp-mma GEMM (2-pass fp16): acc += (Ah+Al)(64x256 smem) @ Wh[n][256] ----
__device__ __forceinline__ void mma_gemm(
    const __half* Ah, const __half* Al, __half* Bh,
    const __half* gWh, float (&acc)[16][4], int tid)
{
    int warp = tid >> 5, lane = tid & 31;
    int m0 = (warp >> 1) * 16, n0 = (warp & 1) * 128;
    int g = lane >> 2, kp = (lane & 3) * 2;
    const __half* wh = gWh + tid * 256;

    uint4 rh0 = *(const uint4*)(wh);
    uint4 rh1 = *(const uint4*)(wh + 8);

    for (int kc = 0; kc < 16; kc++) {
        *(uint4*)(Bh + tid * SB)     = rh0;
        *(uint4*)(Bh + tid * SB + 8) = rh1;
        __syncthreads();
        if (kc + 1 < 16) {
            rh0 = *(const uint4*)(wh + (kc + 1) * 16);
            rh1 = *(const uint4*)(wh + (kc + 1) * 16 + 8);
        }
        const __half* ab = Ah + (m0 + g) * SA + kc * 16 + kp;
        const __half* lb = Al + (m0 + g) * SA + kc * 16 + kp;
        unsigned ah0 = *(const unsigned*)ab;
        unsigned ah2 = *(const unsigned*)(ab + 8);
        unsigned ah1 = *(const unsigned*)(ab + 8 * SA);
        unsigned ah3 = *(const unsigned*)(ab + 8 * SA + 8);
        unsigned al0 = *(const unsigned*)lb;
        unsigned al2 = *(const unsigned*)(lb + 8);
        unsigned al1 = *(const unsigned*)(lb + 8 * SA);
        unsigned al3 = *(const unsigned*)(lb + 8 * SA + 8);
#pragma unroll
        for (int nt = 0; nt < 16; nt++) {
            const __half* bb = Bh + (n0 + nt * 8 + g) * SB + kp;
            unsigned bh0 = *(const unsigned*)bb;
            unsigned bh1 = *(const unsigned*)(bb + 8);
            mma_f16(acc[nt], ah0, ah1, ah2, ah3, bh0, bh1);
            mma_f16(acc[nt], al0, al1, al2, al3, bh0, bh1);
        }
        __syncthreads();
    }
}

// ---------------- weight pre-split (fp16 round) ----------------
__global__ void k_prep1(const float* __restrict__ W, int K, int dstoff) {
    int t = blockIdx.x * 256 + threadIdx.x;
    if (t >= 256 * K) return;
    int n = t / K, k = t - n * K;
    g_Wh[dstoff + t] = __float2half_rn(W[(size_t)k * HH + n]);
}

// ---------------- utility kernels ----------------
__global__ void k_zero() {
    int idx = blockIdx.x * blockDim.x + threadIdx.x;
    const int total = NN * HH + NN;
    for (; idx < total; idx += gridDim.x * blockDim.x) {
        if (idx < NN * HH) g_agg[idx] = 0.f;
        else g_deg[idx - NN * HH] = 0.f;
    }
}
__global__ void k_deg(const int* __restrict__ ei) {
    int e = blockIdx.x * 256 + threadIdx.x;
    if (e < NE) atomicAdd(&g_deg[ei[NE + e]], 1.0f);
}
__global__ void k_scale() {
    int idx = blockIdx.x * 256 + threadIdx.x;
    if (idx < NN * HH) g_agg[idx] = g_agg[idx] / fmaxf(g_deg[idx >> 8], 1.0f);
}

// ------- node HMMA GEMM (2-pass fp16): C[M,256] = act(A[M,K] @ W + bias + addC) -------
__global__ __launch_bounds__(256, 2) void k_hgemm(
    const float* __restrict__ A, int M, int K,
    const __half* __restrict__ gWh,
    const float* __restrict__ bias, const float* __restrict__ addC,
    float* __restrict__ C, int relu)
{
    __shared__ __half Ah[64 * SAN], Al[64 * SAN];
    __shared__ __half Bh[256 * SB];
    int tid = threadIdx.x;
    int row0 = blockIdx.x * 64;
    int warp = tid >> 5, lane = tid & 31;
    int m0 = (warp >> 1) * 16, n0 = (warp & 1) * 128;
    int g = lane >> 2, kq = (lane & 3) * 2;
    float acc[16][4];
#pragma unroll
    for (int i = 0; i < 16; i++)
#pragma unroll
        for (int j = 0; j < 4; j++) acc[i][j] = 0.f;

    int ar = tid >> 2, ac = (tid & 3) * 4;
    int arow = row0 + ar;
    if (arow >= M) arow = M - 1;
    const float* Arow = A + (size_t)arow * K;
    const __half* wh = gWh + (size_t)tid * K;

    float4 av = *(const float4*)(Arow + ac);
    uint4 rh0 = *(const uint4*)(wh);
    uint4 rh1 = *(const uint4*)(wh + 8);

    int nch = K >> 4;
    for (int kc = 0; kc < nch; kc++) {
        split_storeS(Ah, Al, SAN, ar, ac, av.x, av.y);
        split_storeS(Ah, Al, SAN, ar, ac + 2, av.z, av.w);
        *(uint4*)(Bh + tid * SB)     = rh0;
        *(uint4*)(Bh + tid * SB + 8) = rh1;
        __syncthreads();
        if (kc + 1 < nch) {
            av = *(const float4*)(Arow + (kc + 1) * 16 + ac);
            rh0 = *(const uint4*)(wh + (kc + 1) * 16);
            rh1 = *(const uint4*)(wh + (kc + 1) * 16 + 8);
        }
        const __half* ab = Ah + (m0 + g) * SAN + kq;
        const __half* lb = Al + (m0 + g) * SAN + kq;
        unsigned ah0 = *(const unsigned*)ab;
        unsigned ah2 = *(const unsigned*)(ab + 8);
        unsigned ah1 = *(const unsigned*)(ab + 8 * SAN);
        unsigned ah3 = *(const unsigned*)(ab + 8 * SAN + 8);
        unsigned al0 = *(const unsigned*)lb;
        unsigned al2 = *(const unsigned*)(lb + 8);
        unsigned al1 = *(const unsigned*)(lb + 8 * SAN);
        unsigned al3 = *(const unsigned*)(lb + 8 * SAN + 8);
#pragma unroll
        for (int nt = 0; nt < 16; nt++) {
            const __half* bb = Bh + (n0 + nt * 8 + g) * SB + kq;
            unsigned bh0 = *(const unsigned*)bb;
            unsigned bh1 = *(const unsigned*)(bb + 8);
            mma_f16(acc[nt], ah0, ah1, ah2, ah3, bh0, bh1);
            mma_f16(acc[nt], al0, al1, al2, al3, bh0, bh1);
        }
        __syncthreads();
    }

    int r0 = row0 + m0 + g, r1 = r0 + 8;
#pragma unroll
    for (int nt = 0; nt < 16; nt++) {
        int c = n0 + nt * 8 + kq;
        float b0 = bias ? bias[c] : 0.f, b1 = bias ? bias[c + 1] : 0.f;
        if (r0 < M) {
            float v0 = acc[nt][0] + b0, v1 = acc[nt][1] + b1;
            if (addC) { v0 += addC[(size_t)r0 * HH + c]; v1 += addC[(size_t)r0 * HH + c + 1]; }
            if (relu) { v0 = fmaxf(v0, 0.f); v1 = fmaxf(v1, 0.f); }
            *(float2*)(C + (size_t)r0 * HH + c) = make_float2(v0, v1);
        }
        if (r1 < M) {
            float v2 = acc[nt][2] + b0, v3 = acc[nt][3] + b1;
            if (addC) { v2 += addC[(size_t)r1 * HH + c]; v3 += addC[(size_t)r1 * HH + c + 1]; }
            if (relu) { v2 = fmaxf(v2, 0.f); v3 = fmaxf(v3, 0.f); }
            *(float2*)(C + (size_t)r1 * HH + c) = make_float2(v2, v3);
        }
    }
}

// ---------------- MMA edge layer 0 ----------------
__global__ __launch_bounds__(256, 2) void k_edge0_mma(
    const int* __restrict__ ei, const float* __restrict__ eattr,
    const float* __restrict__ We0a, const float* __restrict__ be0a,
    const float* __restrict__ be0b)
{
    extern __shared__ __align__(16) unsigned char dsm[];
    __half* Ah = (__half*)dsm;
    __half* Al = Ah + 64 * SA;
    __half* Bh = Al + 64 * SA;
    __shared__ float w3f[256 * 6];
    __shared__ float b0s[256], b1s[256];
    __shared__ int src_s[64], dst_s[64];

    int tid = threadIdx.x;
    int e0 = blockIdx.x * 64;
    if (tid < 64) { src_s[tid] = ei[e0 + tid]; dst_s[tid] = ei[NE + e0 + tid]; }
    b0s[tid] = be0a[tid];
    b1s[tid] = be0b[tid];
    for (int i = tid; i < 1536; i += 256)
        w3f[(i & 255) * 6 + (i >> 8)] = We0a[(size_t)(1024 + (i >> 8)) * HH + (i & 255)];
    __syncthreads();

    {
        int m = tid >> 2, q = tid & 3;
        const float* xs = g_Xs + (size_t)src_s[m] * HH;
        const float* xd = g_Xd + (size_t)dst_s[m] * HH;
        float ear[6];
#pragma unroll
        for (int j = 0; j < 6; j++) ear[j] = eattr[(size_t)(e0 + m) * 6 + j];
        for (int k = q * 64; k < q * 64 + 64; k += 4) {
            float4 a = *(const float4*)(xs + k);
            float4 b = *(const float4*)(xd + k);
            float v[4] = {a.x + b.x, a.y + b.y, a.z + b.z, a.w + b.w};
#pragma unroll
            for (int j2 = 0; j2 < 4; j2++) {
                float t = v[j2] + b0s[k + j2];
#pragma unroll
                for (int j = 0; j < 6; j++) t += ear[j] * w3f[(k + j2) * 6 + j];
                v[j2] = fmaxf(t, 0.f);
            }
            split_storeS(Ah, Al, SA, m, k, v[0], v[1]);
            split_storeS(Ah, Al, SA, m, k + 2, v[2], v[3]);
        }
    }
    __syncthreads();

    float acc[16][4];
#pragma unroll
    for (int i = 0; i < 16; i++)
#pragma unroll
        for (int j = 0; j < 4; j++) acc[i][j] = 0.f;
    mma_gemm(Ah, Al, Bh, g_Wh, acc, tid);

    {
        int warp = tid >> 5, lane = tid & 31;
        int m0 = (warp >> 1) * 16, n0 = (warp & 1) * 128;
        int g = lane >> 2, kq = (lane & 3) * 2;
        int r0 = m0 + g, r1 = m0 + g + 8;
        size_t rb0 = (size_t)(e0 + r0) * HH, rb1 = (size_t)(e0 + r1) * HH;
        size_t ab0 = (size_t)dst_s[r0] * HH, ab1 = (size_t)dst_s[r1] * HH;
#pragma unroll
        for (int nt = 0; nt < 16; nt++) {
            int c = n0 + nt * 8 + kq;
            float2 v0 = make_float2(acc[nt][0] + b1s[c], acc[nt][1] + b1s[c + 1]);
            float2 v1 = make_float2(acc[nt][2] + b1s[c], acc[nt][3] + b1s[c + 1]);
            *(float2*)(g_EA1 + rb0 + c) = v0;
            *(float2*)(g_EA1 + rb1 + c) = v1;
            red2(g_agg + ab0 + c, v0.x, v0.y);
            red2(g_agg + ab1 + c, v1.x, v1.y);
        }
    }
}

// ---------------- MMA edge layer 1 + predictor ----------------
__global__ __launch_bounds__(256, 2) void k_chain2_mma(
    const int* __restrict__ ei,
    const float* __restrict__ be1a, const float* __restrict__ be1b,
    const float* __restrict__ bp1, const float* __restrict__ Wp2,
    const float* __restrict__ bp2, float* __restrict__ out)
{
    extern __shared__ __align__(16) unsigned char dsm[];
    __half* Ah = (__half*)dsm;
    __half* Al = Ah + 64 * SA;
    __half* Bh = Al + 64 * SA;
    __shared__ float b1s[256], b2s[256], bps[256], wp2s[256];
    __shared__ int src_s[64], dst_s[64];
    __shared__ float outp[64];

    int tid = threadIdx.x;
    int e0 = blockIdx.x * 64;
    if (tid < 64) {
        src_s[tid] = ei[e0 + tid];
        dst_s[tid] = ei[NE + e0 + tid];
        outp[tid] = 0.f;
    }
    b1s[tid] = be1a[tid];
    b2s[tid] = be1b[tid];
    bps[tid] = bp1[tid];
    wp2s[tid] = Wp2[tid];
    __syncthreads();

    int warp = tid >> 5, lane = tid & 31;
    int m0 = (warp >> 1) * 16, n0 = (warp & 1) * 128;
    int g = lane >> 2, kq = (lane & 3) * 2;
    int r0 = m0 + g, r1 = m0 + g + 8;

    {
        int m = tid >> 2, q = tid & 3;
        const float* er = g_EA1 + (size_t)(e0 + m) * HH;
        for (int k = q * 64; k < q * 64 + 64; k += 4) {
            float4 a = *(const float4*)(er + k);
            split_storeS(Ah, Al, SA, m, k, a.x, a.y);
            split_storeS(Ah, Al, SA, m, k + 2, a.z, a.w);
        }
    }
    __syncthreads();

    float acc[16][4];
#pragma unroll
    for (int i = 0; i < 16; i++)
#pragma unroll
        for (int j = 0; j < 4; j++) acc[i][j] = 0.f;

    // GEMM1: EA1 @ We1a[512:768]; h1 = relu(. + be1a + Y1[src] + Y2[dst])
    mma_gemm(Ah, Al, Bh, g_Wh + 65536, acc, tid);
    {
        const float* y1a = g_Y1 + (size_t)src_s[r0] * HH;
        const float* y2a = g_Y2 + (size_t)dst_s[r0] * HH;
        const float* y1b = g_Y1 + (size_t)src_s[r1] * HH;
        const float* y2b = g_Y2 + (size_t)dst_s[r1] * HH;
#pragma unroll
        for (int nt = 0; nt < 16; nt++) {
            int c = n0 + nt * 8 + kq;
            float2 p1 = *(const float2*)(y1a + c);
            float2 p2 = *(const float2*)(y2a + c);
            float2 p3 = *(const float2*)(y1b + c);
            float2 p4 = *(const float2*)(y2b + c);
            float v0 = fmaxf(acc[nt][0] + b1s[c]     + p1.x + p2.x, 0.f);
            float v1 = fmaxf(acc[nt][1] + b1s[c + 1] + p1.y + p2.y, 0.f);
            float v2 = fmaxf(acc[nt][2] + b1s[c]     + p3.x + p4.x, 0.f);
            float v3 = fmaxf(acc[nt][3] + b1s[c + 1] + p3.y + p4.y, 0.f);
            split_storeS(Ah, Al, SA, r0, c, v0, v1);
            split_storeS(Ah, Al, SA, r1, c, v2, v3);
            acc[nt][0] = 0.f; acc[nt][1] = 0.f; acc[nt][2] = 0.f; acc[nt][3] = 0.f;
        }
    }
    __syncthreads();

    // GEMM2: h1 @ We1b; EA2 = . + be1b + EA1
    mma_gemm(Ah, Al, Bh, g_Wh + 131072, acc, tid);
    {
        const float* era = g_EA1 + (size_t)(e0 + r0) * HH;
        const float* erb = g_EA1 + (size_t)(e0 + r1) * HH;
#pragma unroll
        for (int nt = 0; nt < 16; nt++) {
            int c = n0 + nt * 8 + kq;
            float2 q0 = *(const float2*)(era + c);
            float2 q1 = *(const float2*)(erb + c);
            float v0 = acc[nt][0] + b2s[c]     + q0.x;
            float v1 = acc[nt][1] + b2s[c + 1] + q0.y;
            float v2 = acc[nt][2] + b2s[c]     + q1.x;
            float v3 = acc[nt][3] + b2s[c + 1] + q1.y;
            split_storeS(Ah, Al, SA, r0, c, v0, v1);
            split_storeS(Ah, Al, SA, r1, c, v2, v3);
            acc[nt][0] = 0.f; acc[nt][1] = 0.f; acc[nt][2] = 0.f; acc[nt][3] = 0.f;
        }
    }
    __syncthreads();

    // GEMM3: EA2 @ Wp1; leaky-relu, dot wp2
    mma_gemm(Ah, Al, Bh, g_Wh + 196608, acc, tid);
    {
        float p0 = 0.f, p1 = 0.f;
#pragma unroll
        for (int nt = 0; nt < 16; nt++) {
            int c = n0 + nt * 8 + kq;
            float v0 = acc[nt][0] + bps[c];
            float v1 = acc[nt][1] + bps[c + 1];
            float v2 = acc[nt][2] + bps[c];
            float v3 = acc[nt][3] + bps[c + 1];
            v0 = (v0 > 0.f) ? v0 : 0.01f * v0;
            v1 = (v1 > 0.f) ? v1 : 0.01f * v1;
            v2 = (v2 > 0.f) ? v2 : 0.01f * v2;
            v3 = (v3 > 0.f) ? v3 : 0.01f * v3;
            p0 += v0 * wp2s[c] + v1 * wp2s[c + 1];
            p1 += v2 * wp2s[c] + v3 * wp2s[c + 1];
        }
        p0 += __shfl_xor_sync(0xffffffffu, p0, 1);
        p0 += __shfl_xor_sync(0xffffffffu, p0, 2);
        p1 += __shfl_xor_sync(0xffffffffu, p1, 1);
        p1 += __shfl_xor_sync(0xffffffffu, p1, 2);
        if ((lane & 3) == 0) {
            atomicAdd(&outp[r0], p0);
            atomicAdd(&outp[r1], p1);
        }
    }
    __syncthreads();
    if (tid < 64) out[e0 + tid] = outp[tid] + bp2[0];
}

// ---------------- host launcher ----------------
extern "C" void kernel_launch(void* const* d_in, const int* in_sizes, int n_in,
                              void* d_out, int out_size)
{
    (void)in_sizes; (void)n_in; (void)out_size;
    const float* x    = (const float*)d_in[0];
    const int*   ei   = (const int*)  d_in[1];
    const float* ea   = (const float*)d_in[2];
    const float* We0a = (const float*)d_in[3];
    const float* be0a = (const float*)d_in[4];
    const float* We0b = (const float*)d_in[5];
    const float* be0b = (const float*)d_in[6];
    const float* Wn0a = (const float*)d_in[7];
    const float* bn0a = (const float*)d_in[8];
    const float* Wn0b = (const float*)d_in[9];
    const float* bn0b = (const float*)d_in[10];
    const float* We1a = (const float*)d_in[11];
    const float* be1a = (const float*)d_in[12];
    const float* We1b = (const float*)d_in[13];
    const float* be1b = (const float*)d_in[14];
    const float* Wp1  = (const float*)d_in[19];
    const float* bp1  = (const float*)d_in[20];
    const float* Wp2  = (const float*)d_in[21];
    const float* bp2  = (const float*)d_in[22];
    float* out = (float*)d_out;

    const int DSM = (2 * 64 * SA + 256 * SB) * 2;  // 79872 bytes
    cudaFuncSetAttribute(k_edge0_mma,  cudaFuncAttributeMaxDynamicSharedMemorySize, DSM);
    cudaFuncSetAttribute(k_chain2_mma, cudaFuncAttributeMaxDynamicSharedMemorySize, DSM);

    void *p_Xs, *p_Xd, *p_agg, *p_P, *p_x1h, *p_x1, *p_Y1, *p_Y2, *p_Wh;
    cudaGetSymbolAddress(&p_Xs,  g_Xs);
    cudaGetSymbolAddress(&p_Xd,  g_Xd);
    cudaGetSymbolAddress(&p_agg, g_agg);
    cudaGetSymbolAddress(&p_P,   g_P);
    cudaGetSymbolAddress(&p_x1h, g_x1h);
    cudaGetSymbolAddress(&p_x1,  g_x1);
    cudaGetSymbolAddress(&p_Y1,  g_Y1);
    cudaGetSymbolAddress(&p_Y2,  g_Y2);
    cudaGetSymbolAddress(&p_Wh,  g_Wh);
    const __half* Wh = (const __half*)p_Wh;

    // pre-round all weights to fp16 [n][k] pool
    k_prep1<<<256, 256>>>(We0b,            256, 0);
    k_prep1<<<256, 256>>>(We1a + 512 * HH, 256, 65536);
    k_prep1<<<256, 256>>>(We1b,            256, 131072);
    k_prep1<<<256, 256>>>(Wp1,             256, 196608);
    k_prep1<<<512, 256>>>(We0a,            512, 262144);
    k_prep1<<<512, 256>>>(We0a + 512 * HH, 512, 393216);
    k_prep1<<<512, 256>>>(Wn0a,            512, 524288);
    k_prep1<<<256, 256>>>(Wn0a + 512 * HH, 256, 655360);
    k_prep1<<<256, 256>>>(Wn0b,            256, 720896);
    k_prep1<<<256, 256>>>(We1a,            256, 786432);
    k_prep1<<<256, 256>>>(We1a + 256 * HH, 256, 851968);

    k_zero<<<2048, 256>>>();
    k_deg<<<NE / 256, 256>>>(ei);

    const int gM = (NN + 63) / 64;

    // layer-0 edge precompute: Xs = x@We0a[0:512], Xd = x@We0a[512:1024]
    k_hgemm<<<gM, 256>>>(x, NN, FIN, Wh + 262144, nullptr, nullptr, (float*)p_Xs, 0);
    k_hgemm<<<gM, 256>>>(x, NN, FIN, Wh + 393216, nullptr, nullptr, (float*)p_Xd, 0);

    // fused edge layer 0 (HMMA) -> EA1, agg
    k_edge0_mma<<<NE / 64, 256, DSM>>>(ei, ea, We0a, be0a, be0b);
    k_scale<<<(NN * HH + 255) / 256, 256>>>();

    // node MLP 0: x1 = relu(x@Wn0a_top + agg@Wn0a_bot + bn0a) @ Wn0b + bn0b
    k_hgemm<<<gM, 256>>>(x, NN, FIN, Wh + 524288, nullptr, nullptr, (float*)p_P, 0);
    k_hgemm<<<gM, 256>>>((const float*)p_agg, NN, HH, Wh + 655360, bn0a,
                         (const float*)p_P, (float*)p_x1h, 1);
    k_hgemm<<<gM, 256>>>((const float*)p_x1h, NN, HH, Wh + 720896, bn0b,
                         nullptr, (float*)p_x1, 0);

    // layer-1 edge precompute: Y1 = x1@We1a[0:256], Y2 = x1@We1a[256:512]
    k_hgemm<<<gM, 256>>>((const float*)p_x1, NN, HH, Wh + 786432, nullptr, nullptr, (float*)p_Y1, 0);
    k_hgemm<<<gM, 256>>>((const float*)p_x1, NN, HH, Wh + 851968, nullptr, nullptr, (float*)p_Y2, 0);

    // fused edge layer 1 + residual + predictor (HMMA)
    k_chain2_mma<<<NE / 64, 256, DSM>>>(ei, be1a, be1b, bp1, Wp2, bp2, out);
}

// round 14
// speedup vs baseline: 2.2263x; 1.0898x over previous
#include <cuda_runtime.h>
#include <cuda_fp16.h>
#include <cstdint>
#include <cstddef>

#define NN 10000
#define NE 320000
#define FIN 512
#define HH 256
#define SA 264   // A smem stride (fp16 elems): 528B/row -> 4-bank shift/row
#define SB 24    // B smem stride (fp16 elems): 48B/row -> 12-bank shift/row
#define SAN 20   // node A chunk smem stride

// ---------------- scratch ----------------
__device__ float g_Xs[NN * HH];
__device__ float g_Xd[NN * HH];
__device__ float g_agg[NN * HH];
__device__ float g_deg[NN];
__device__ float g_P[NN * HH];
__device__ float g_x1h[NN * HH];
__device__ float g_x1[NN * HH];
__device__ float g_Y1[NN * HH];
__device__ float g_Y2[NN * HH];
__device__ float g_EA1[(size_t)NE * HH];
// fp16 weight pool, layout [n][k] (k contiguous)
// offsets: 0:We0b 65536:We1a[512:768] 131072:We1b 196608:Wp1
//          262144:We0a[0:512] 393216:We0a[512:1024] 524288:Wn0a[0:512]
//          655360:Wn0a[512:768] 720896:Wn0b 786432:We1a[0:256] 851968:We1a[256:512]
__device__ __align__(128) __half g_Wh[917504];

// ---------------- helpers ----------------
__device__ __forceinline__ void mma_f16(float* c, unsigned a0, unsigned a1, unsigned a2,
                                        unsigned a3, unsigned b0, unsigned b1) {
    asm volatile(
        "mma.sync.aligned.m16n8k16.row.col.f32.f16.f16.f32 "
        "{%0,%1,%2,%3}, {%4,%5,%6,%7}, {%8,%9}, {%0,%1,%2,%3};"
        : "+f"(c[0]), "+f"(c[1]), "+f"(c[2]), "+f"(c[3])
        : "r"(a0), "r"(a1), "r"(a2), "r"(a3), "r"(b0), "r"(b1));
}
__device__ __forceinline__ unsigned packh2(float v0, float v1) {
    __half h0 = __float2half_rn(v0), h1 = __float2half_rn(v1);
    return (unsigned)__half_as_ushort(h0) | ((unsigned)__half_as_ushort(h1) << 16);
}
__device__ __forceinline__ void round_store(__half* Ah, int stride, int m, int k,
                                            float v0, float v1) {
    *(unsigned*)(Ah + m * stride + k) = packh2(v0, v1);
}
__device__ __forceinline__ void red2(float* p, float x, float y) {
    asm volatile("red.global.add.v2.f32 [%0], {%1,%2};" :: "l"(p), "f"(x), "f"(y) : "memory");
}

// ---- edge warp-mma GEMM (1-pass fp16, 512 thr, M=128): acc += A @ Wh[n][256] ----
__device__ __forceinline__ void mma_gemm(
    const __half* Ah, __half* Bh, const __half* gWh, float (&acc)[16][4], int tid)
{
    int warp = tid >> 5, lane = tid & 31;
    int m0 = (warp >> 1) * 16, n0 = (warp & 1) * 128;
    int g = lane >> 2, kp = (lane & 3) * 2;
    int bn = tid >> 1, b8 = (tid & 1) * 8;
    const __half* wh = gWh + bn * 256 + b8;

    uint4 rh = *(const uint4*)wh;
    for (int kc = 0; kc < 16; kc++) {
        *(uint4*)(Bh + bn * SB + b8) = rh;
        __syncthreads();
        if (kc + 1 < 16) rh = *(const uint4*)(wh + (kc + 1) * 16);
        const __half* ab = Ah + (m0 + g) * SA + kc * 16 + kp;
        unsigned a0 = *(const unsigned*)ab;
        unsigned a2 = *(const unsigned*)(ab + 8);
        unsigned a1 = *(const unsigned*)(ab + 8 * SA);
        unsigned a3 = *(const unsigned*)(ab + 8 * SA + 8);
#pragma unroll
        for (int nt = 0; nt < 16; nt++) {
            const __half* bb = Bh + (n0 + nt * 8 + g) * SB + kp;
            unsigned b0 = *(const unsigned*)bb;
            unsigned b1 = *(const unsigned*)(bb + 8);
            mma_f16(acc[nt], a0, a1, a2, a3, b0, b1);
        }
        __syncthreads();
    }
}

// ---------------- weight prep (fp16 round, [n][k]) ----------------
__global__ void k_prep1(const float* __restrict__ W, int K, int dstoff) {
    int t = blockIdx.x * 256 + threadIdx.x;
    if (t >= 256 * K) return;
    int n = t / K, k = t - n * K;
    g_Wh[dstoff + t] = __float2half_rn(W[(size_t)k * HH + n]);
}

// ---------------- utility kernels ----------------
__global__ void k_zero() {
    int idx = blockIdx.x * blockDim.x + threadIdx.x;
    const int total = NN * HH + NN;
    for (; idx < total; idx += gridDim.x * blockDim.x) {
        if (idx < NN * HH) g_agg[idx] = 0.f;
        else g_deg[idx - NN * HH] = 0.f;
    }
}
__global__ void k_deg(const int* __restrict__ ei) {
    int e = blockIdx.x * 256 + threadIdx.x;
    if (e < NE) atomicAdd(&g_deg[ei[NE + e]], 1.0f);
}
__global__ void k_scale() {
    int idx = blockIdx.x * 256 + threadIdx.x;
    if (idx < NN * HH) g_agg[idx] = g_agg[idx] / fmaxf(g_deg[idx >> 8], 1.0f);
}

// ------- node HMMA GEMM (1-pass fp16): C[M,256] = act(A[M,K] @ W + bias + addC) -------
__global__ __launch_bounds__(256, 2) void k_hgemm(
    const float* __restrict__ A, int M, int K,
    const __half* __restrict__ gWh,
    const float* __restrict__ bias, const float* __restrict__ addC,
    float* __restrict__ C, int relu)
{
    __shared__ __half Ah[64 * SAN];
    __shared__ __half Bh[256 * SB];
    int tid = threadIdx.x;
    int row0 = blockIdx.x * 64;
    int warp = tid >> 5, lane = tid & 31;
    int m0 = (warp >> 1) * 16, n0 = (warp & 1) * 128;
    int g = lane >> 2, kq = (lane & 3) * 2;
    float acc[16][4];
#pragma unroll
    for (int i = 0; i < 16; i++)
#pragma unroll
        for (int j = 0; j < 4; j++) acc[i][j] = 0.f;

    int ar = tid >> 2, ac = (tid & 3) * 4;
    int arow = row0 + ar;
    if (arow >= M) arow = M - 1;
    const float* Arow = A + (size_t)arow * K;
    const __half* wh = gWh + (size_t)tid * K;

    float4 av = *(const float4*)(Arow + ac);
    uint4 rh0 = *(const uint4*)(wh);
    uint4 rh1 = *(const uint4*)(wh + 8);

    int nch = K >> 4;
    for (int kc = 0; kc < nch; kc++) {
        round_store(Ah, SAN, ar, ac, av.x, av.y);
        round_store(Ah, SAN, ar, ac + 2, av.z, av.w);
        *(uint4*)(Bh + tid * SB)     = rh0;
        *(uint4*)(Bh + tid * SB + 8) = rh1;
        __syncthreads();
        if (kc + 1 < nch) {
            av = *(const float4*)(Arow + (kc + 1) * 16 + ac);
            rh0 = *(const uint4*)(wh + (kc + 1) * 16);
            rh1 = *(const uint4*)(wh + (kc + 1) * 16 + 8);
        }
        const __half* ab = Ah + (m0 + g) * SAN + kq;
        unsigned a0 = *(const unsigned*)ab;
        unsigned a2 = *(const unsigned*)(ab + 8);
        unsigned a1 = *(const unsigned*)(ab + 8 * SAN);
        unsigned a3 = *(const unsigned*)(ab + 8 * SAN + 8);
#pragma unroll
        for (int nt = 0; nt < 16; nt++) {
            const __half* bb = Bh + (n0 + nt * 8 + g) * SB + kq;
            unsigned b0 = *(const unsigned*)bb;
            unsigned b1 = *(const unsigned*)(bb + 8);
            mma_f16(acc[nt], a0, a1, a2, a3, b0, b1);
        }
        __syncthreads();
    }

    int r0 = row0 + m0 + g, r1 = r0 + 8;
#pragma unroll
    for (int nt = 0; nt < 16; nt++) {
        int c = n0 + nt * 8 + kq;
        float b0 = bias ? bias[c] : 0.f, b1 = bias ? bias[c + 1] : 0.f;
        if (r0 < M) {
            float v0 = acc[nt][0] + b0, v1 = acc[nt][1] + b1;
            if (addC) { v0 += addC[(size_t)r0 * HH + c]; v1 += addC[(size_t)r0 * HH + c + 1]; }
            if (relu) { v0 = fmaxf(v0, 0.f); v1 = fmaxf(v1, 0.f); }
            *(float2*)(C + (size_t)r0 * HH + c) = make_float2(v0, v1);
        }
        if (r1 < M) {
            float v2 = acc[nt][2] + b0, v3 = acc[nt][3] + b1;
            if (addC) { v2 += addC[(size_t)r1 * HH + c]; v3 += addC[(size_t)r1 * HH + c + 1]; }
            if (relu) { v2 = fmaxf(v2, 0.f); v3 = fmaxf(v3, 0.f); }
            *(float2*)(C + (size_t)r1 * HH + c) = make_float2(v2, v3);
        }
    }
}

// ---------------- MMA edge layer 0 (512 thr, 128 edges/CTA) ----------------
__global__ __launch_bounds__(512, 1) void k_edge0_mma(
    const int* __restrict__ ei, const float* __restrict__ eattr,
    const float* __restrict__ We0a, const float* __restrict__ be0a,
    const float* __restrict__ be0b)
{
    extern __shared__ __align__(16) unsigned char dsm[];
    __half* Ah = (__half*)dsm;               // 128 * SA
    __half* Bh = Ah + 128 * SA;              // 256 * SB
    __shared__ float w3f[256 * 6];
    __shared__ float b0s[256], b1s[256];
    __shared__ int src_s[128], dst_s[128];

    int tid = threadIdx.x;
    int e0 = blockIdx.x * 128;
    if (tid < 128) { src_s[tid] = ei[e0 + tid]; dst_s[tid] = ei[NE + e0 + tid]; }
    if (tid < 256) { b0s[tid] = be0a[tid]; b1s[tid] = be0b[tid]; }
    for (int i = tid; i < 1536; i += 512)
        w3f[(i & 255) * 6 + (i >> 8)] = We0a[(size_t)(1024 + (i >> 8)) * HH + (i & 255)];
    __syncthreads();

    // build h0 tile [128 x 256] (fp16-rounded)
    {
        int m = tid >> 2, q = tid & 3;
        const float* xs = g_Xs + (size_t)src_s[m] * HH;
        const float* xd = g_Xd + (size_t)dst_s[m] * HH;
        float ear[6];
#pragma unroll
        for (int j = 0; j < 6; j++) ear[j] = eattr[(size_t)(e0 + m) * 6 + j];
        for (int k = q * 64; k < q * 64 + 64; k += 4) {
            float4 a = *(const float4*)(xs + k);
            float4 b = *(const float4*)(xd + k);
            float v[4] = {a.x + b.x, a.y + b.y, a.z + b.z, a.w + b.w};
#pragma unroll
            for (int j2 = 0; j2 < 4; j2++) {
                float t = v[j2] + b0s[k + j2];
#pragma unroll
                for (int j = 0; j < 6; j++) t += ear[j] * w3f[(k + j2) * 6 + j];
                v[j2] = fmaxf(t, 0.f);
            }
            round_store(Ah, SA, m, k, v[0], v[1]);
            round_store(Ah, SA, m, k + 2, v[2], v[3]);
        }
    }
    __syncthreads();

    float acc[16][4];
#pragma unroll
    for (int i = 0; i < 16; i++)
#pragma unroll
        for (int j = 0; j < 4; j++) acc[i][j] = 0.f;
    mma_gemm(Ah, Bh, g_Wh, acc, tid);

    // epilogue: bias, store EA1, vector-atomic agg
    {
        int warp = tid >> 5, lane = tid & 31;
        int m0 = (warp >> 1) * 16, n0 = (warp & 1) * 128;
        int g = lane >> 2, kq = (lane & 3) * 2;
        int r0 = m0 + g, r1 = m0 + g + 8;
        size_t rb0 = (size_t)(e0 + r0) * HH, rb1 = (size_t)(e0 + r1) * HH;
        size_t ab0 = (size_t)dst_s[r0] * HH, ab1 = (size_t)dst_s[r1] * HH;
#pragma unroll
        for (int nt = 0; nt < 16; nt++) {
            int c = n0 + nt * 8 + kq;
            float2 v0 = make_float2(acc[nt][0] + b1s[c], acc[nt][1] + b1s[c + 1]);
            float2 v1 = make_float2(acc[nt][2] + b1s[c], acc[nt][3] + b1s[c + 1]);
            *(float2*)(g_EA1 + rb0 + c) = v0;
            *(float2*)(g_EA1 + rb1 + c) = v1;
            red2(g_agg + ab0 + c, v0.x, v0.y);
            red2(g_agg + ab1 + c, v1.x, v1.y);
        }
    }
}

// ---------------- MMA edge layer 1 + predictor (512 thr, 128 edges/CTA) ----------------
__global__ __launch_bounds__(512, 1) void k_chain2_mma(
    const int* __restrict__ ei,
    const float* __restrict__ be1a, const float* __restrict__ be1b,
    const float* __restrict__ bp1, const float* __restrict__ Wp2,
    const float* __restrict__ bp2, float* __restrict__ out)
{
    extern __shared__ __align__(16) unsigned char dsm[];
    __half* Ah = (__half*)dsm;               // 128 * SA
    __half* Bh = Ah + 128 * SA;              // 256 * SB
    __shared__ float b1s[256], b2s[256], bps[256], wp2s[256];
    __shared__ int src_s[128], dst_s[128];
    __shared__ float outp[128];

    int tid = threadIdx.x;
    int e0 = blockIdx.x * 128;
    if (tid < 128) {
        src_s[tid] = ei[e0 + tid];
        dst_s[tid] = ei[NE + e0 + tid];
        outp[tid] = 0.f;
    }
    if (tid < 256) {
        b1s[tid] = be1a[tid];
        b2s[tid] = be1b[tid];
        bps[tid] = bp1[tid];
        wp2s[tid] = Wp2[tid];
    }
    __syncthreads();

    int warp = tid >> 5, lane = tid & 31;
    int m0 = (warp >> 1) * 16, n0 = (warp & 1) * 128;
    int g = lane >> 2, kq = (lane & 3) * 2;
    int r0 = m0 + g, r1 = m0 + g + 8;

    // stage A = EA1 tile (fp16-rounded)
    {
        int m = tid >> 2, q = tid & 3;
        const float* er = g_EA1 + (size_t)(e0 + m) * HH;
        for (int k = q * 64; k < q * 64 + 64; k += 4) {
            float4 a = *(const float4*)(er + k);
            round_store(Ah, SA, m, k, a.x, a.y);
            round_store(Ah, SA, m, k + 2, a.z, a.w);
        }
    }
    __syncthreads();

    float acc[16][4];
#pragma unroll
    for (int i = 0; i < 16; i++)
#pragma unroll
        for (int j = 0; j < 4; j++) acc[i][j] = 0.f;

    // GEMM1: EA1 @ We1a[512:768]; h1 = relu(. + be1a + Y1[src] + Y2[dst])
    mma_gemm(Ah, Bh, g_Wh + 65536, acc, tid);
    {
        const float* y1a = g_Y1 + (size_t)src_s[r0] * HH;
        const float* y2a = g_Y2 + (size_t)dst_s[r0] * HH;
        const float* y1b = g_Y1 + (size_t)src_s[r1] * HH;
        const float* y2b = g_Y2 + (size_t)dst_s[r1] * HH;
#pragma unroll
        for (int nt = 0; nt < 16; nt++) {
            int c = n0 + nt * 8 + kq;
            float2 p1 = *(const float2*)(y1a + c);
            float2 p2 = *(const float2*)(y2a + c);
            float2 p3 = *(const float2*)(y1b + c);
            float2 p4 = *(const float2*)(y2b + c);
            float v0 = fmaxf(acc[nt][0] + b1s[c]     + p1.x + p2.x, 0.f);
            float v1 = fmaxf(acc[nt][1] + b1s[c + 1] + p1.y + p2.y, 0.f);
            float v2 = fmaxf(acc[nt][2] + b1s[c]     + p3.x + p4.x, 0.f);
            float v3 = fmaxf(acc[nt][3] + b1s[c + 1] + p3.y + p4.y, 0.f);
            round_store(Ah, SA, r0, c, v0, v1);
            round_store(Ah, SA, r1, c, v2, v3);
            acc[nt][0] = 0.f; acc[nt][1] = 0.f; acc[nt][2] = 0.f; acc[nt][3] = 0.f;
        }
    }
    __syncthreads();

    // GEMM2: h1 @ We1b; EA2 = . + be1b + EA1 (fp32 residual from global)
    mma_gemm(Ah, Bh, g_Wh + 131072, acc, tid);
    {
        const float* era = g_EA1 + (size_t)(e0 + r0) * HH;
        const float* erb = g_EA1 + (size_t)(e0 + r1) * HH;
#pragma unroll
        for (int nt = 0; nt < 16; nt++) {
            int c = n0 + nt * 8 + kq;
            float2 q0 = *(const float2*)(era + c);
            float2 q1 = *(const float2*)(erb + c);
            float v0 = acc[nt][0] + b2s[c]     + q0.x;
            float v1 = acc[nt][1] + b2s[c + 1] + q0.y;
            float v2 = acc[nt][2] + b2s[c]     + q1.x;
            float v3 = acc[nt][3] + b2s[c + 1] + q1.y;
            round_store(Ah, SA, r0, c, v0, v1);
            round_store(Ah, SA, r1, c, v2, v3);
            acc[nt][0] = 0.f; acc[nt][1] = 0.f; acc[nt][2] = 0.f; acc[nt][3] = 0.f;
        }
    }
    __syncthreads();

    // GEMM3: EA2 @ Wp1; leaky-relu, dot wp2
    mma_gemm(Ah, Bh, g_Wh + 196608, acc, tid);
    {
        float p0 = 0.f, p1 = 0.f;
#pragma unroll
        for (int nt = 0; nt < 16; nt++) {
            int c = n0 + nt * 8 + kq;
            float v0 = acc[nt][0] + bps[c];
            float v1 = acc[nt][1] + bps[c + 1];
            float v2 = acc[nt][2] + bps[c];
            float v3 = acc[nt][3] + bps[c + 1];
            v0 = (v0 > 0.f) ? v0 : 0.01f * v0;
            v1 = (v1 > 0.f) ? v1 : 0.01f * v1;
            v2 = (v2 > 0.f) ? v2 : 0.01f * v2;
            v3 = (v3 > 0.f) ? v3 : 0.01f * v3;
            p0 += v0 * wp2s[c] + v1 * wp2s[c + 1];
            p1 += v2 * wp2s[c] + v3 * wp2s[c + 1];
        }
        p0 += __shfl_xor_sync(0xffffffffu, p0, 1);
        p0 += __shfl_xor_sync(0xffffffffu, p0, 2);
        p1 += __shfl_xor_sync(0xffffffffu, p1, 1);
        p1 += __shfl_xor_sync(0xffffffffu, p1, 2);
        if ((lane & 3) == 0) {
            atomicAdd(&outp[r0], p0);
            atomicAdd(&outp[r1], p1);
        }
    }
    __syncthreads();
    if (tid < 128) out[e0 + tid] = outp[tid] + bp2[0];
}

// ---------------- host launcher ----------------
extern "C" void kernel_launch(void* const* d_in, const int* in_sizes, int n_in,
                              void* d_out, int out_size)
{
    (void)in_sizes; (void)n_in; (void)out_size;
    const float* x    = (const float*)d_in[0];
    const int*   ei   = (const int*)  d_in[1];
    const float* ea   = (const float*)d_in[2];
    const float* We0a = (const float*)d_in[3];
    const float* be0a = (const float*)d_in[4];
    const float* We0b = (const float*)d_in[5];
    const float* be0b = (const float*)d_in[6];
    const float* Wn0a = (const float*)d_in[7];
    const float* bn0a = (const float*)d_in[8];
    const float* Wn0b = (const float*)d_in[9];
    const float* bn0b = (const float*)d_in[10];
    const float* We1a = (const float*)d_in[11];
    const float* be1a = (const float*)d_in[12];
    const float* We1b = (const float*)d_in[13];
    const float* be1b = (const float*)d_in[14];
    const float* Wp1  = (const float*)d_in[19];
    const float* bp1  = (const float*)d_in[20];
    const float* Wp2  = (const float*)d_in[21];
    const float* bp2  = (const float*)d_in[22];
    float* out = (float*)d_out;

    const int DSM = 128 * SA * 2 + 256 * SB * 2;  // 79872 bytes
    cudaFuncSetAttribute(k_edge0_mma,  cudaFuncAttributeMaxDynamicSharedMemorySize, DSM);
    cudaFuncSetAttribute(k_chain2_mma, cudaFuncAttributeMaxDynamicSharedMemorySize, DSM);

    void *p_Xs, *p_Xd, *p_agg, *p_P, *p_x1h, *p_x1, *p_Y1, *p_Y2, *p_Wh;
    cudaGetSymbolAddress(&p_Xs,  g_Xs);
    cudaGetSymbolAddress(&p_Xd,  g_Xd);
    cudaGetSymbolAddress(&p_agg, g_agg);
    cudaGetSymbolAddress(&p_P,   g_P);
    cudaGetSymbolAddress(&p_x1h, g_x1h);
    cudaGetSymbolAddress(&p_x1,  g_x1);
    cudaGetSymbolAddress(&p_Y1,  g_Y1);
    cudaGetSymbolAddress(&p_Y2,  g_Y2);
    cudaGetSymbolAddress(&p_Wh,  g_Wh);
    const __half* Wh = (const __half*)p_Wh;

    // pre-round all weights to fp16 [n][k] pool
    k_prep1<<<256, 256>>>(We0b,            256, 0);
    k_prep1<<<256, 256>>>(We1a + 512 * HH, 256, 65536);
    k_prep1<<<256, 256>>>(We1b,            256, 131072);
    k_prep1<<<256, 256>>>(Wp1,             256, 196608);
    k_prep1<<<512, 256>>>(We0a,            512, 262144);
    k_prep1<<<512, 256>>>(We0a + 512 * HH, 512, 393216);
    k_prep1<<<512, 256>>>(Wn0a,            512, 524288);
    k_prep1<<<256, 256>>>(Wn0a + 512 * HH, 256, 655360);
    k_prep1<<<256, 256>>>(Wn0b,            256, 720896);
    k_prep1<<<256, 256>>>(We1a,            256, 786432);
    k_prep1<<<256, 256>>>(We1a + 256 * HH, 256, 851968);

    k_zero<<<2048, 256>>>();
    k_deg<<<NE / 256, 256>>>(ei);

    const int gM = (NN + 63) / 64;

    // layer-0 edge precompute: Xs = x@We0a[0:512], Xd = x@We0a[512:1024]
    k_hgemm<<<gM, 256>>>(x, NN, FIN, Wh + 262144, nullptr, nullptr, (float*)p_Xs, 0);
    k_hgemm<<<gM, 256>>>(x, NN, FIN, Wh + 393216, nullptr, nullptr, (float*)p_Xd, 0);

    // fused edge layer 0 (HMMA) -> EA1, agg
    k_edge0_mma<<<NE / 128, 512, DSM>>>(ei, ea, We0a, be0a, be0b);
    k_scale<<<(NN * HH + 255) / 256, 256>>>();

    // node MLP 0: x1 = relu(x@Wn0a_top + agg@Wn0a_bot + bn0a) @ Wn0b + bn0b
    k_hgemm<<<gM, 256>>>(x, NN, FIN, Wh + 524288, nullptr, nullptr, (float*)p_P, 0);
    k_hgemm<<<gM, 256>>>((const float*)p_agg, NN, HH, Wh + 655360, bn0a,
                         (const float*)p_P, (float*)p_x1h, 1);
    k_hgemm<<<gM, 256>>>((const float*)p_x1h, NN, HH, Wh + 720896, bn0b,
                         nullptr, (float*)p_x1, 0);

    // layer-1 edge precompute: Y1 = x1@We1a[0:256], Y2 = x1@We1a[256:512]
    k_hgemm<<<gM, 256>>>((const float*)p_x1, NN, HH, Wh + 786432, nullptr, nullptr, (float*)p_Y1, 0);
    k_hgemm<<<gM, 256>>>((const float*)p_x1, NN, HH, Wh + 851968, nullptr, nullptr, (float*)p_Y2, 0);

    // fused edge layer 1 + residual + predictor (HMMA)
    k_chain2_mma<<<NE / 128, 512, DSM>>>(ei, be1a, be1b, bp1, Wp2, bp2, out);
}

// round 15
// speedup vs baseline: 2.4880x; 1.1176x over previous
#include <cuda_runtime.h>
#include <cuda_fp16.h>
#include <cstdint>
#include <cstddef>

#define NN 10000
#define NE 320000
#define FIN 512
#define HH 256
#define SA 264   // A smem stride (fp16): 528B/row -> ldmatrix conflict-free
#define SB 24    // B smem stride (fp16): 48B/row  -> ldmatrix conflict-free
#define SAN 24   // node A chunk stride (16B-aligned rows for ldmatrix)

// ---------------- scratch ----------------
__device__ float g_Xs[NN * HH];
__device__ float g_Xd[NN * HH];
__device__ float g_agg[NN * HH];
__device__ float g_deg[NN];
__device__ float g_P[NN * HH];
__device__ float g_x1h[NN * HH];
__device__ float g_x1[NN * HH];
__device__ float g_Y1[NN * HH];
__device__ float g_Y2[NN * HH];
__device__ float g_EA1[(size_t)NE * HH];
// fp16 weight pool, layout [n][k] (k contiguous)
__device__ __align__(128) __half g_Wh[917504];

// ---------------- helpers ----------------
__device__ __forceinline__ void mma_f16(float* c, unsigned a0, unsigned a1, unsigned a2,
                                        unsigned a3, unsigned b0, unsigned b1) {
    asm volatile(
        "mma.sync.aligned.m16n8k16.row.col.f32.f16.f16.f32 "
        "{%0,%1,%2,%3}, {%4,%5,%6,%7}, {%8,%9}, {%0,%1,%2,%3};"
        : "+f"(c[0]), "+f"(c[1]), "+f"(c[2]), "+f"(c[3])
        : "r"(a0), "r"(a1), "r"(a2), "r"(a3), "r"(b0), "r"(b1));
}
__device__ __forceinline__ void ldsm4(unsigned& r0, unsigned& r1, unsigned& r2, unsigned& r3,
                                      uint32_t a) {
    asm volatile("ldmatrix.sync.aligned.m8n8.x4.shared.b16 {%0,%1,%2,%3}, [%4];"
                 : "=r"(r0), "=r"(r1), "=r"(r2), "=r"(r3) : "r"(a));
}
__device__ __forceinline__ uint32_t smem_addr(const void* p) {
    return (uint32_t)__cvta_generic_to_shared(p);
}
__device__ __forceinline__ unsigned packh2(float v0, float v1) {
    __half h0 = __float2half_rn(v0), h1 = __float2half_rn(v1);
    return (unsigned)__half_as_ushort(h0) | ((unsigned)__half_as_ushort(h1) << 16);
}
__device__ __forceinline__ void round_store(__half* Ah, int stride, int m, int k,
                                            float v0, float v1) {
    *(unsigned*)(Ah + m * stride + k) = packh2(v0, v1);
}
__device__ __forceinline__ void red2(float* p, float x, float y) {
    asm volatile("red.global.add.v2.f32 [%0], {%1,%2};" :: "l"(p), "f"(x), "f"(y) : "memory");
}

// ---- edge warp-mma GEMM: ldmatrix fragments + double-buffered B, 1 sync/chunk ----
// acc[16][4] += A(128x256 smem, stride SA) @ W[n][256]
__device__ __forceinline__ void mma_gemm(
    const __half* Ah, __half* Bh, const __half* gWh, float (&acc)[16][4], int tid)
{
    int warp = tid >> 5, lane = tid & 31;
    int m0 = (warp >> 1) * 16, n0 = (warp & 1) * 128;
    int bn = tid >> 1, b8 = (tid & 1) * 8;
    const __half* wh = gWh + bn * 256 + b8;
    const int BUFB = 256 * SB * 2;  // bytes per B buffer

    uint32_t aAddr = smem_addr(Ah + (m0 + (lane & 7) + (lane & 8)) * SA) + (lane >> 4) * 16;
    int brow = (lane & 7) + ((lane >> 4) << 3);
    uint32_t bAddr = smem_addr(Bh + (n0 + brow) * SB) + ((lane >> 3) & 1) * 16;
    __half* stsP = Bh + bn * SB + b8;

    uint4 rh = *(const uint4*)wh;           // chunk 0
    *(uint4*)stsP = rh;                     // stage chunk 0 -> buf 0
    rh = *(const uint4*)(wh + 16);          // prefetch chunk 1
    __syncthreads();

    for (int kc = 0; kc < 16; kc++) {
        if (kc + 1 < 16) {
            *(uint4*)((char*)stsP + ((kc + 1) & 1) * BUFB) = rh;    // stage kc+1
            if (kc + 2 < 16) rh = *(const uint4*)(wh + (kc + 2) * 16);
        }
        uint32_t bufOff = (uint32_t)(kc & 1) * BUFB;
        unsigned a0, a1, a2, a3;
        ldsm4(a0, a1, a2, a3, aAddr + kc * 32);
#pragma unroll
        for (int ntp = 0; ntp < 8; ntp++) {
            unsigned b0, b1, b2, b3;
            ldsm4(b0, b1, b2, b3, bAddr + bufOff + ntp * (16 * SB * 2));
            mma_f16(acc[2 * ntp],     a0, a1, a2, a3, b0, b1);
            mma_f16(acc[2 * ntp + 1], a0, a1, a2, a3, b2, b3);
        }
        __syncthreads();
    }
}

// ---------------- weight prep (fp16 round, [n][k]) ----------------
__global__ void k_prep1(const float* __restrict__ W, int K, int dstoff) {
    int t = blockIdx.x * 256 + threadIdx.x;
    if (t >= 256 * K) return;
    int n = t / K, k = t - n * K;
    g_Wh[dstoff + t] = __float2half_rn(W[(size_t)k * HH + n]);
}

// ---------------- utility kernels ----------------
__global__ void k_zero() {
    int idx = blockIdx.x * blockDim.x + threadIdx.x;
    const int total = NN * HH + NN;
    for (; idx < total; idx += gridDim.x * blockDim.x) {
        if (idx < NN * HH) g_agg[idx] = 0.f;
        else g_deg[idx - NN * HH] = 0.f;
    }
}
__global__ void k_deg(const int* __restrict__ ei) {
    int e = blockIdx.x * 256 + threadIdx.x;
    if (e < NE) atomicAdd(&g_deg[ei[NE + e]], 1.0f);
}
__global__ void k_scale() {
    int idx = blockIdx.x * 256 + threadIdx.x;
    if (idx < NN * HH) g_agg[idx] = g_agg[idx] / fmaxf(g_deg[idx >> 8], 1.0f);
}

// ------- node HMMA GEMM (1-pass fp16 + ldmatrix): C = act(A[M,K] @ W + bias + addC) -------
__global__ __launch_bounds__(256, 2) void k_hgemm(
    const float* __restrict__ A, int M, int K,
    const __half* __restrict__ gWh,
    const float* __restrict__ bias, const float* __restrict__ addC,
    float* __restrict__ C, int relu)
{
    __shared__ __half Ah[64 * SAN];
    __shared__ __half Bh[256 * SB];
    int tid = threadIdx.x;
    int row0 = blockIdx.x * 64;
    int warp = tid >> 5, lane = tid & 31;
    int m0 = (warp >> 1) * 16, n0 = (warp & 1) * 128;
    int g = lane >> 2, kq = (lane & 3) * 2;
    float acc[16][4];
#pragma unroll
    for (int i = 0; i < 16; i++)
#pragma unroll
        for (int j = 0; j < 4; j++) acc[i][j] = 0.f;

    int ar = tid >> 2, ac = (tid & 3) * 4;
    int arow = row0 + ar;
    if (arow >= M) arow = M - 1;
    const float* Arow = A + (size_t)arow * K;
    const __half* wh = gWh + (size_t)tid * K;

    uint32_t aAddr = smem_addr(Ah + (m0 + (lane & 7) + (lane & 8)) * SAN) + (lane >> 4) * 16;
    int brow = (lane & 7) + ((lane >> 4) << 3);
    uint32_t bAddr = smem_addr(Bh + (n0 + brow) * SB) + ((lane >> 3) & 1) * 16;

    float4 av = *(const float4*)(Arow + ac);
    uint4 rh0 = *(const uint4*)(wh);
    uint4 rh1 = *(const uint4*)(wh + 8);

    int nch = K >> 4;
    for (int kc = 0; kc < nch; kc++) {
        round_store(Ah, SAN, ar, ac, av.x, av.y);
        round_store(Ah, SAN, ar, ac + 2, av.z, av.w);
        *(uint4*)(Bh + tid * SB)     = rh0;
        *(uint4*)(Bh + tid * SB + 8) = rh1;
        __syncthreads();
        if (kc + 1 < nch) {
            av = *(const float4*)(Arow + (kc + 1) * 16 + ac);
            rh0 = *(const uint4*)(wh + (kc + 1) * 16);
            rh1 = *(const uint4*)(wh + (kc + 1) * 16 + 8);
        }
        unsigned a0, a1, a2, a3;
        ldsm4(a0, a1, a2, a3, aAddr);
#pragma unroll
        for (int ntp = 0; ntp < 8; ntp++) {
            unsigned b0, b1, b2, b3;
            ldsm4(b0, b1, b2, b3, bAddr + ntp * (16 * SB * 2));
            mma_f16(acc[2 * ntp],     a0, a1, a2, a3, b0, b1);
            mma_f16(acc[2 * ntp + 1], a0, a1, a2, a3, b2, b3);
        }
        __syncthreads();
    }

    int r0 = row0 + m0 + g, r1 = r0 + 8;
#pragma unroll
    for (int nt = 0; nt < 16; nt++) {
        int c = n0 + nt * 8 + kq;
        float b0 = bias ? bias[c] : 0.f, b1 = bias ? bias[c + 1] : 0.f;
        if (r0 < M) {
            float v0 = acc[nt][0] + b0, v1 = acc[nt][1] + b1;
            if (addC) { v0 += addC[(size_t)r0 * HH + c]; v1 += addC[(size_t)r0 * HH + c + 1]; }
            if (relu) { v0 = fmaxf(v0, 0.f); v1 = fmaxf(v1, 0.f); }
            *(float2*)(C + (size_t)r0 * HH + c) = make_float2(v0, v1);
        }
        if (r1 < M) {
            float v2 = acc[nt][2] + b0, v3 = acc[nt][3] + b1;
            if (addC) { v2 += addC[(size_t)r1 * HH + c]; v3 += addC[(size_t)r1 * HH + c + 1]; }
            if (relu) { v2 = fmaxf(v2, 0.f); v3 = fmaxf(v3, 0.f); }
            *(float2*)(C + (size_t)r1 * HH + c) = make_float2(v2, v3);
        }
    }
}

// ---------------- MMA edge layer 0 (512 thr, 128 edges/CTA) ----------------
__global__ __launch_bounds__(512, 1) void k_edge0_mma(
    const int* __restrict__ ei, const float* __restrict__ eattr,
    const float* __restrict__ We0a, const float* __restrict__ be0a,
    const float* __restrict__ be0b)
{
    extern __shared__ __align__(16) unsigned char dsm[];
    __half* Ah = (__half*)dsm;               // 128 * SA
    __half* Bh = Ah + 128 * SA;              // 2 * 256 * SB
    __shared__ float w3f[256 * 6];
    __shared__ float b0s[256], b1s[256];
    __shared__ int src_s[128], dst_s[128];

    int tid = threadIdx.x;
    int e0 = blockIdx.x * 128;
    if (tid < 128) { src_s[tid] = ei[e0 + tid]; dst_s[tid] = ei[NE + e0 + tid]; }
    if (tid < 256) { b0s[tid] = be0a[tid]; b1s[tid] = be0b[tid]; }
    for (int i = tid; i < 1536; i += 512)
        w3f[(i & 255) * 6 + (i >> 8)] = We0a[(size_t)(1024 + (i >> 8)) * HH + (i & 255)];
    __syncthreads();

    // build h0 tile [128 x 256] (fp16-rounded)
    {
        int m = tid >> 2, q = tid & 3;
        const float* xs = g_Xs + (size_t)src_s[m] * HH;
        const float* xd = g_Xd + (size_t)dst_s[m] * HH;
        float ear[6];
#pragma unroll
        for (int j = 0; j < 6; j++) ear[j] = eattr[(size_t)(e0 + m) * 6 + j];
        for (int k = q * 64; k < q * 64 + 64; k += 4) {
            float4 a = *(const float4*)(xs + k);
            float4 b = *(const float4*)(xd + k);
            float v[4] = {a.x + b.x, a.y + b.y, a.z + b.z, a.w + b.w};
#pragma unroll
            for (int j2 = 0; j2 < 4; j2++) {
                float t = v[j2] + b0s[k + j2];
#pragma unroll
                for (int j = 0; j < 6; j++) t += ear[j] * w3f[(k + j2) * 6 + j];
                v[j2] = fmaxf(t, 0.f);
            }
            round_store(Ah, SA, m, k, v[0], v[1]);
            round_store(Ah, SA, m, k + 2, v[2], v[3]);
        }
    }
    __syncthreads();

    float acc[16][4];
#pragma unroll
    for (int i = 0; i < 16; i++)
#pragma unroll
        for (int j = 0; j < 4; j++) acc[i][j] = 0.f;
    mma_gemm(Ah, Bh, g_Wh, acc, tid);

    // epilogue: bias, store EA1, vector-atomic agg
    {
        int warp = tid >> 5, lane = tid & 31;
        int m0 = (warp >> 1) * 16, n0 = (warp & 1) * 128;
        int g = lane >> 2, kq = (lane & 3) * 2;
        int r0 = m0 + g, r1 = m0 + g + 8;
        size_t rb0 = (size_t)(e0 + r0) * HH, rb1 = (size_t)(e0 + r1) * HH;
        size_t ab0 = (size_t)dst_s[r0] * HH, ab1 = (size_t)dst_s[r1] * HH;
#pragma unroll
        for (int nt = 0; nt < 16; nt++) {
            int c = n0 + nt * 8 + kq;
            float2 v0 = make_float2(acc[nt][0] + b1s[c], acc[nt][1] + b1s[c + 1]);
            float2 v1 = make_float2(acc[nt][2] + b1s[c], acc[nt][3] + b1s[c + 1]);
            *(float2*)(g_EA1 + rb0 + c) = v0;
            *(float2*)(g_EA1 + rb1 + c) = v1;
            red2(g_agg + ab0 + c, v0.x, v0.y);
            red2(g_agg + ab1 + c, v1.x, v1.y);
        }
    }
}

// ---------------- MMA edge layer 1 + predictor (512 thr, 128 edges/CTA) ----------------
__global__ __launch_bounds__(512, 1) void k_chain2_mma(
    const int* __restrict__ ei,
    const float* __restrict__ be1a, const float* __restrict__ be1b,
    const float* __restrict__ bp1, const float* __restrict__ Wp2,
    const float* __restrict__ bp2, float* __restrict__ out)
{
    extern __shared__ __align__(16) unsigned char dsm[];
    __half* Ah = (__half*)dsm;               // 128 * SA
    __half* Bh = Ah + 128 * SA;              // 2 * 256 * SB
    __shared__ float b1s[256], b2s[256], bps[256], wp2s[256];
    __shared__ int src_s[128], dst_s[128];
    __shared__ float outp[128];

    int tid = threadIdx.x;
    int e0 = blockIdx.x * 128;
    if (tid < 128) {
        src_s[tid] = ei[e0 + tid];
        dst_s[tid] = ei[NE + e0 + tid];
        outp[tid] = 0.f;
    }
    if (tid < 256) {
        b1s[tid] = be1a[tid];
        b2s[tid] = be1b[tid];
        bps[tid] = bp1[tid];
        wp2s[tid] = Wp2[tid];
    }
    __syncthreads();

    int warp = tid >> 5, lane = tid & 31;
    int m0 = (warp >> 1) * 16, n0 = (warp & 1) * 128;
    int g = lane >> 2, kq = (lane & 3) * 2;
    int r0 = m0 + g, r1 = m0 + g + 8;

    // stage A = EA1 tile (fp16-rounded)
    {
        int m = tid >> 2, q = tid & 3;
        const float* er = g_EA1 + (size_t)(e0 + m) * HH;
        for (int k = q * 64; k < q * 64 + 64; k += 4) {
            float4 a = *(const float4*)(er + k);
            round_store(Ah, SA, m, k, a.x, a.y);
            round_store(Ah, SA, m, k + 2, a.z, a.w);
        }
    }
    __syncthreads();

    float acc[16][4];
#pragma unroll
    for (int i = 0; i < 16; i++)
#pragma unroll
        for (int j = 0; j < 4; j++) acc[i][j] = 0.f;

    // GEMM1: EA1 @ We1a[512:768]; h1 = relu(. + be1a + Y1[src] + Y2[dst])
    mma_gemm(Ah, Bh, g_Wh + 65536, acc, tid);
    {
        const float* y1a = g_Y1 + (size_t)src_s[r0] * HH;
        const float* y2a = g_Y2 + (size_t)dst_s[r0] * HH;
        const float* y1b = g_Y1 + (size_t)src_s[r1] * HH;
        const float* y2b = g_Y2 + (size_t)dst_s[r1] * HH;
#pragma unroll
        for (int nt = 0; nt < 16; nt++) {
            int c = n0 + nt * 8 + kq;
            float2 p1 = *(const float2*)(y1a + c);
            float2 p2 = *(const float2*)(y2a + c);
            float2 p3 = *(const float2*)(y1b + c);
            float2 p4 = *(const float2*)(y2b + c);
            float v0 = fmaxf(acc[nt][0] + b1s[c]     + p1.x + p2.x, 0.f);
            float v1 = fmaxf(acc[nt][1] + b1s[c + 1] + p1.y + p2.y, 0.f);
            float v2 = fmaxf(acc[nt][2] + b1s[c]     + p3.x + p4.x, 0.f);
            float v3 = fmaxf(acc[nt][3] + b1s[c + 1] + p3.y + p4.y, 0.f);
            round_store(Ah, SA, r0, c, v0, v1);
            round_store(Ah, SA, r1, c, v2, v3);
            acc[nt][0] = 0.f; acc[nt][1] = 0.f; acc[nt][2] = 0.f; acc[nt][3] = 0.f;
        }
    }
    __syncthreads();

    // GEMM2: h1 @ We1b; EA2 = . + be1b + EA1 (fp32 residual from global)
    mma_gemm(Ah, Bh, g_Wh + 131072, acc, tid);
    {
        const float* era = g_EA1 + (size_t)(e0 + r0) * HH;
        const float* erb = g_EA1 + (size_t)(e0 + r1) * HH;
#pragma unroll
        for (int nt = 0; nt < 16; nt++) {
            int c = n0 + nt * 8 + kq;
            float2 q0 = *(const float2*)(era + c);
            float2 q1 = *(const float2*)(erb + c);
            float v0 = acc[nt][0] + b2s[c]     + q0.x;
            float v1 = acc[nt][1] + b2s[c + 1] + q0.y;
            float v2 = acc[nt][2] + b2s[c]     + q1.x;
            float v3 = acc[nt][3] + b2s[c + 1] + q1.y;
            round_store(Ah, SA, r0, c, v0, v1);
            round_store(Ah, SA, r1, c, v2, v3);
            acc[nt][0] = 0.f; acc[nt][1] = 0.f; acc[nt][2] = 0.f; acc[nt][3] = 0.f;
        }
    }
    __syncthreads();

    // GEMM3: EA2 @ Wp1; leaky-relu, dot wp2
    mma_gemm(Ah, Bh, g_Wh + 196608, acc, tid);
    {
        float p0 = 0.f, p1 = 0.f;
#pragma unroll
        for (int nt = 0; nt < 16; nt++) {
            int c = n0 + nt * 8 + kq;
            float v0 = acc[nt][0] + bps[c];
            float v1 = acc[nt][1] + bps[c + 1];
            float v2 = acc[nt][2] + bps[c];
            float v3 = acc[nt][3] + bps[c + 1];
            v0 = (v0 > 0.f) ? v0 : 0.01f * v0;
            v1 = (v1 > 0.f) ? v1 : 0.01f * v1;
            v2 = (v2 > 0.f) ? v2 : 0.01f * v2;
            v3 = (v3 > 0.f) ? v3 : 0.01f * v3;
            p0 += v0 * wp2s[c] + v1 * wp2s[c + 1];
            p1 += v2 * wp2s[c] + v3 * wp2s[c + 1];
        }
        p0 += __shfl_xor_sync(0xffffffffu, p0, 1);
        p0 += __shfl_xor_sync(0xffffffffu, p0, 2);
        p1 += __shfl_xor_sync(0xffffffffu, p1, 1);
        p1 += __shfl_xor_sync(0xffffffffu, p1, 2);
        if ((lane & 3) == 0) {
            atomicAdd(&outp[r0], p0);
            atomicAdd(&outp[r1], p1);
        }
    }
    __syncthreads();
    if (tid < 128) out[e0 + tid] = outp[tid] + bp2[0];
}

// ---------------- host launcher ----------------
extern "C" void kernel_launch(void* const* d_in, const int* in_sizes, int n_in,
                              void* d_out, int out_size)
{
    (void)in_sizes; (void)n_in; (void)out_size;
    const float* x    = (const float*)d_in[0];
    const int*   ei   = (const int*)  d_in[1];
    const float* ea   = (const float*)d_in[2];
    const float* We0a = (const float*)d_in[3];
    const float* be0a = (const float*)d_in[4];
    const float* We0b = (const float*)d_in[5];
    const float* be0b = (const float*)d_in[6];
    const float* Wn0a = (const float*)d_in[7];
    const float* bn0a = (const float*)d_in[8];
    const float* Wn0b = (const float*)d_in[9];
    const float* bn0b = (const float*)d_in[10];
    const float* We1a = (const float*)d_in[11];
    const float* be1a = (const float*)d_in[12];
    const float* We1b = (const float*)d_in[13];
    const float* be1b = (const float*)d_in[14];
    const float* Wp1  = (const float*)d_in[19];
    const float* bp1  = (const float*)d_in[20];
    const float* Wp2  = (const float*)d_in[21];
    const float* bp2  = (const float*)d_in[22];
    float* out = (float*)d_out;

    const int DSM = 128 * SA * 2 + 2 * 256 * SB * 2;  // 92160 bytes
    cudaFuncSetAttribute(k_edge0_mma,  cudaFuncAttributeMaxDynamicSharedMemorySize, DSM);
    cudaFuncSetAttribute(k_chain2_mma, cudaFuncAttributeMaxDynamicSharedMemorySize, DSM);

    void *p_Xs, *p_Xd, *p_agg, *p_P, *p_x1h, *p_x1, *p_Y1, *p_Y2, *p_Wh;
    cudaGetSymbolAddress(&p_Xs,  g_Xs);
    cudaGetSymbolAddress(&p_Xd,  g_Xd);
    cudaGetSymbolAddress(&p_agg, g_agg);
    cudaGetSymbolAddress(&p_P,   g_P);
    cudaGetSymbolAddress(&p_x1h, g_x1h);
    cudaGetSymbolAddress(&p_x1,  g_x1);
    cudaGetSymbolAddress(&p_Y1,  g_Y1);
    cudaGetSymbolAddress(&p_Y2,  g_Y2);
    cudaGetSymbolAddress(&p_Wh,  g_Wh);
    const __half* Wh = (const __half*)p_Wh;

    // pre-round all weights to fp16 [n][k] pool
    k_prep1<<<256, 256>>>(We0b,            256, 0);
    k_prep1<<<256, 256>>>(We1a + 512 * HH, 256, 65536);
    k_prep1<<<256, 256>>>(We1b,            256, 131072);
    k_prep1<<<256, 256>>>(Wp1,             256, 196608);
    k_prep1<<<512, 256>>>(We0a,            512, 262144);
    k_prep1<<<512, 256>>>(We0a + 512 * HH, 512, 393216);
    k_prep1<<<512, 256>>>(Wn0a,            512, 524288);
    k_prep1<<<256, 256>>>(Wn0a + 512 * HH, 256, 655360);
    k_prep1<<<256, 256>>>(Wn0b,            256, 720896);
    k_prep1<<<256, 256>>>(We1a,            256, 786432);
    k_prep1<<<256, 256>>>(We1a + 256 * HH, 256, 851968);

    k_zero<<<2048, 256>>>();
    k_deg<<<NE / 256, 256>>>(ei);

    const int gM = (NN + 63) / 64;

    // layer-0 edge precompute: Xs = x@We0a[0:512], Xd = x@We0a[512:1024]
    k_hgemm<<<gM, 256>>>(x, NN, FIN, Wh + 262144, nullptr, nullptr, (float*)p_Xs, 0);
    k_hgemm<<<gM, 256>>>(x, NN, FIN, Wh + 393216, nullptr, nullptr, (float*)p_Xd, 0);

    // fused edge layer 0 (HMMA) -> EA1, agg
    k_edge0_mma<<<NE / 128, 512, DSM>>>(ei, ea, We0a, be0a, be0b);
    k_scale<<<(NN * HH + 255) / 256, 256>>>();

    // node MLP 0: x1 = relu(x@Wn0a_top + agg@Wn0a_bot + bn0a) @ Wn0b + bn0b
    k_hgemm<<<gM, 256>>>(x, NN, FIN, Wh + 524288, nullptr, nullptr, (float*)p_P, 0);
    k_hgemm<<<gM, 256>>>((const float*)p_agg, NN, HH, Wh + 655360, bn0a,
                         (const float*)p_P, (float*)p_x1h, 1);
    k_hgemm<<<gM, 256>>>((const float*)p_x1h, NN, HH, Wh + 720896, bn0b,
                         nullptr, (float*)p_x1, 0);

    // layer-1 edge precompute: Y1 = x1@We1a[0:256], Y2 = x1@We1a[256:512]
    k_hgemm<<<gM, 256>>>((const float*)p_x1, NN, HH, Wh + 786432, nullptr, nullptr, (float*)p_Y1, 0);
    k_hgemm<<<gM, 256>>>((const float*)p_x1, NN, HH, Wh + 851968, nullptr, nullptr, (float*)p_Y2, 0);

    // fused edge layer 1 + residual + predictor (HMMA)
    k_chain2_mma<<<NE / 128, 512, DSM>>>(ei, be1a, be1b, bp1, Wp2, bp2, out);
}